// round 9
// baseline (speedup 1.0000x reference)
#include <cuda_runtime.h>
#include <cuda_fp16.h>
#include <cstdint>
#include <math.h>

#define DMODEL 1024
#define BATCH  8
#define SEQ    512
#define NHEAD  16
#define DKH    64
#define MTOK   4096
#define DFF    4096
#define NCLIP  64
#define LN_EPS 1e-5f

typedef __half half_t;

// ---------------------------------------------------------------------------
// PTX helpers (arch-agnostic: mma.sync / ldmatrix / cp.async only)
// ---------------------------------------------------------------------------
__device__ __forceinline__ uint32_t smem_u32(const void* p) {
    uint32_t a;
    asm("{ .reg .u64 t; cvta.to.shared.u64 t, %1; cvt.u32.u64 %0, t; }" : "=r"(a) : "l"(p));
    return a;
}

#define LDSM4(r, a) \
    asm volatile("ldmatrix.sync.aligned.m8n8.x4.shared.b16 {%0,%1,%2,%3}, [%4];" \
        : "=r"((r)[0]), "=r"((r)[1]), "=r"((r)[2]), "=r"((r)[3]) : "r"(a))

#define LDSM4T(r, a) \
    asm volatile("ldmatrix.sync.aligned.m8n8.x4.trans.shared.b16 {%0,%1,%2,%3}, [%4];" \
        : "=r"((r)[0]), "=r"((r)[1]), "=r"((r)[2]), "=r"((r)[3]) : "r"(a))

#define MMA16816(c, a, b0, b1) \
    asm volatile("mma.sync.aligned.m16n8k16.row.col.f32.f16.f16.f32 " \
        "{%0,%1,%2,%3}, {%4,%5,%6,%7}, {%8,%9}, {%0,%1,%2,%3};" \
        : "+f"((c)[0]), "+f"((c)[1]), "+f"((c)[2]), "+f"((c)[3]) \
        : "r"((a)[0]), "r"((a)[1]), "r"((a)[2]), "r"((a)[3]), "r"(b0), "r"(b1))

#define CPASYNC16(d, s) asm volatile("cp.async.cg.shared.global [%0], [%1], 16;" :: "r"(d), "l"(s))
#define CPCOMMIT()      asm volatile("cp.async.commit_group;" ::: "memory")
#define CPWAIT(n)       asm volatile("cp.async.wait_group %0;" :: "n"(n) : "memory")

__device__ __forceinline__ uint32_t packh2(float x, float y) {
    __half2 h = __floats2half2_rn(x, y);
    return *(uint32_t*)&h;
}

// ---------------------------------------------------------------------------
// Device scratch
// ---------------------------------------------------------------------------
#define WT_TOT (34u * 1024u * 1024u)
__device__ half_t g_wt[WT_TOT];
__device__ half_t g_xh[MTOK * DMODEL];
__device__ half_t g_hh[MTOK * DMODEL];
__device__ half_t g_ah[MTOK * DMODEL];
__device__ half_t g_fh[MTOK * DFF];
__device__ half_t g_qkvh[3 * 128 * SEQ * DKH];
__device__ half_t g_q[MTOK * DMODEL];
__device__ half_t g_k[MTOK * DMODEL];
__device__ half_t g_v[MTOK * DMODEL];
__device__ half_t g_t1[MTOK * DMODEL];
__device__ half_t g_t2[MTOK * DMODEL];
__device__ half_t g_t3[MTOK * DMODEL];
__device__ float  g_xb[MTOK * DMODEL];

// weight offsets (units of 1M elements) inside g_wt
#define M1 (1024u * 1024u)
#define DDC (1024u * 1024u)
#define OFF_ST  0u
#define OFF_SW3 (6u * M1)
#define OFF_TW3 (7u * M1)
#define OFF_FW  (8u * M1)
#define OFF_AW  (10u * M1)
#define OFF_W1  (18u * M1)
#define OFF_W2  (26u * M1)

// ---------------------------------------------------------------------------
// fp16 HMMA GEMM, BK=64, 3-stage cp.async, 2 CTAs/SM, persistent tile loop.
// MODE 0: standard; MODE 1: QKV head-major scatter;
// MODE 2: six fp16 buffers by col/1024; MODE 3: z-batched out-proj.
// ---------------------------------------------------------------------------
#define STAGES 3
#define STAGE_BYTES 32768
#define SMEM_GEMM (STAGES * STAGE_BYTES)
#define GEMM_MAXGRID 296

template<int MODE>
__global__ __launch_bounds__(256, 2)
void gemm_hmma(const half_t* __restrict__ A, const half_t* __restrict__ B,
               const half_t* __restrict__ A2, const half_t* __restrict__ B2,
               const float* __restrict__ bias, const float* __restrict__ bias2,
               const float* __restrict__ R, float* Cf, half_t* Ch,
               int M, int N, int K, int relu, int ldC, int ntx,
               half_t* q0, half_t* q1, half_t* q2, half_t* q3, half_t* q4, half_t* q5)
{
    extern __shared__ char smem[];
    uint32_t sb = smem_u32(smem);
    const int tid = threadIdx.x;
    const int lane = tid & 31, warp = tid >> 5;
    const int wm = (warp >> 2) * 64;
    const int wn = (warp & 3) * 32;

    if (MODE == 3 && blockIdx.z == 1) { A = A2; B = B2; bias = bias2; }

    int segr[4], segc[4];
#pragma unroll
    for (int i = 0; i < 4; i++) { int s = tid + i * 256; segr[i] = s >> 3; segc[i] = s & 7; }

    int rA[4], swA[4];
#pragma unroll
    for (int mt = 0; mt < 4; mt++) {
        int r = wm + mt * 16 + (lane & 15);
        rA[mt] = r; swA[mt] = r & 7;
    }
    int rB[2], swB[2];
#pragma unroll
    for (int n2 = 0; n2 < 2; n2++) {
        int r = wn + n2 * 16 + (lane & 7) + ((lane >> 4) << 3);
        rB[n2] = r; swB[n2] = r & 7;
    }
    const int csA = lane >> 4;
    const int csB = (lane >> 3) & 1;
    const int NT = K >> 6;
    const int nty = M >> 7;
    const int ntiles = ntx * nty;

#define GISSUE(kt, st) do { \
    uint32_t sA_ = sb + (st) * STAGE_BYTES; \
    uint32_t sB_ = sA_ + 16384; \
    _Pragma("unroll") for (int i = 0; i < 4; i++) { \
        int r_ = segr[i], c_ = segc[i]; \
        uint32_t sw_ = (uint32_t)((c_ ^ (r_ & 7)) << 4); \
        CPASYNC16(sA_ + r_ * 128 + sw_, A + (size_t)(row0 + r_) * K + (size_t)(kt) * 64 + c_ * 8); \
        CPASYNC16(sB_ + r_ * 128 + sw_, B + (size_t)(col0 + r_) * K + (size_t)(kt) * 64 + c_ * 8); \
    } \
    CPCOMMIT(); } while (0)

    for (int tile = blockIdx.x; tile < ntiles; tile += gridDim.x) {
        const int row0 = (tile / ntx) * 128;
        const int col0 = (tile % ntx) * 128;

        float acc[4][4][4];
#pragma unroll
        for (int mt = 0; mt < 4; mt++)
#pragma unroll
            for (int nt = 0; nt < 4; nt++)
#pragma unroll
                for (int i = 0; i < 4; i++) acc[mt][nt][i] = 0.f;

        __syncthreads();   // protect stage buffers from previous tile's readers
        GISSUE(0, 0);
        GISSUE(1, 1);

        for (int kt = 0; kt < NT; kt++) {
            if (kt == NT - 1) { CPWAIT(0); } else { CPWAIT(1); }
            __syncthreads();
            if (kt + 2 < NT) GISSUE(kt + 2, (kt + 2) % 3);

            uint32_t sA = sb + (kt % 3) * STAGE_BYTES;
            uint32_t sB = sA + 16384;
#pragma unroll
            for (int k16 = 0; k16 < 4; k16++) {
                uint32_t ra[4][4], rb[2][4];
#pragma unroll
                for (int mt = 0; mt < 4; mt++)
                    LDSM4(ra[mt], sA + rA[mt] * 128 + ((((k16 << 1) + csA) ^ swA[mt]) << 4));
#pragma unroll
                for (int n2 = 0; n2 < 2; n2++)
                    LDSM4(rb[n2], sB + rB[n2] * 128 + ((((k16 << 1) + csB) ^ swB[n2]) << 4));
#pragma unroll
                for (int mt = 0; mt < 4; mt++)
#pragma unroll
                    for (int nt = 0; nt < 4; nt++)
                        MMA16816(acc[mt][nt], ra[mt],
                                 rb[nt >> 1][(nt & 1) * 2], rb[nt >> 1][(nt & 1) * 2 + 1]);
            }
        }

        // Epilogue
        half_t* obuf = nullptr;
        if (MODE == 2) {
            int bsel = col0 >> 10;
            obuf = (bsel == 0) ? q0 : (bsel == 1) ? q1 : (bsel == 2) ? q2 :
                   (bsel == 3) ? q3 : (bsel == 4) ? q4 : q5;
        }
        const int cbase = (MODE == 3) ? (int)blockIdx.z * 1024 : 0;
#pragma unroll
        for (int mt = 0; mt < 4; mt++) {
            int rg = row0 + wm + mt * 16 + (lane >> 2);
#pragma unroll
            for (int nt = 0; nt < 4; nt++) {
                int c = col0 + wn + nt * 8 + (lane & 3) * 2;
                float* a = acc[mt][nt];
#pragma unroll
                for (int h = 0; h < 2; h++) {
                    int row = rg + h * 8;
                    float v0 = a[h * 2], v1 = a[h * 2 + 1];
                    if (MODE == 0) {
                        if (bias) { v0 += bias[c]; v1 += bias[c + 1]; }
                        if (R) {
                            float2 rr = *(const float2*)(R + (size_t)row * N + c);
                            v0 += rr.x; v1 += rr.y;
                        }
                        if (relu) { v0 = fmaxf(v0, 0.f); v1 = fmaxf(v1, 0.f); }
                        if (Cf) {
                            float2 o; o.x = v0; o.y = v1;
                            *(float2*)(Cf + (size_t)row * ldC + c) = o;
                        }
                        if (Ch)
                            *(__half2*)(Ch + (size_t)row * ldC + c) = __floats2half2_rn(v0, v1);
                    } else if (MODE == 1) {
                        v0 += bias[c]; v1 += bias[c + 1];
                        int qkv = c >> 10, hh_ = (c >> 6) & 15, d = c & 63;
                        int b = row >> 9, srow = row & 511;
                        size_t dst = (((size_t)(qkv * 128 + b * 16 + hh_) * 512) + srow) * 64 + d;
                        *(__half2*)(Ch + dst) = __floats2half2_rn(v0, v1);
                    } else if (MODE == 2) {
                        float b0v = (c < 3072) ? bias[c] : bias2[c - 3072];
                        float b1v = (c + 1 < 3072) ? bias[c + 1] : bias2[c + 1 - 3072];
                        *(__half2*)(obuf + (size_t)row * 1024 + (c & 1023)) =
                            __floats2half2_rn(v0 + b0v, v1 + b1v);
                    } else { // MODE 3
                        v0 += bias[c]; v1 += bias[c + 1];
                        *(__half2*)(Ch + (size_t)row * ldC + cbase + c) = __floats2half2_rn(v0, v1);
                    }
                }
            }
        }
    }
}

// ---------------------------------------------------------------------------
// Flash attention (encoder): per (b,h) 512x512, fp16 mma, online softmax.
// ---------------------------------------------------------------------------
#define FLD 72
#define SMEM_FLASH (3 * 128 * FLD * 2 + 512)

__global__ __launch_bounds__(256)
void flash_attn(const half_t* __restrict__ qkvh, const int* __restrict__ mask,
                half_t* __restrict__ out)
{
    extern __shared__ char sm[];
    half_t* Qs = (half_t*)sm;
    half_t* Ks = Qs + 128 * FLD;
    half_t* Vs = Ks + 128 * FLD;
    float*  mf = (float*)(Vs + 128 * FLD);

    const int bh = blockIdx.y, qt = blockIdx.x;
    const int b = bh >> 4, hd = bh & 15;
    const int tid = threadIdx.x, lane = tid & 31, warp = tid >> 5;
    const int m0 = warp * 16;

    const half_t* Qg = qkvh + (((size_t)(0 * 128 + bh) * 512) + qt * 128) * 64;
    const half_t* Kg = qkvh + ((size_t)(1 * 128 + bh) * 512) * 64;
    const half_t* Vg = qkvh + ((size_t)(2 * 128 + bh) * 512) * 64;

    for (int i = tid; i < 1024; i += 256) {
        int r = i >> 3, cs = i & 7;
        *(uint4*)(Qs + r * FLD + cs * 8) = *(const uint4*)(Qg + r * 64 + cs * 8);
    }
    __syncthreads();

    uint32_t qf[4][4];
#pragma unroll
    for (int kb = 0; kb < 4; kb++)
        LDSM4(qf[kb], smem_u32(Qs + (m0 + (lane & 15)) * FLD + kb * 16 + (lane >> 4) * 8));

    float mrow[2] = {-1e30f, -1e30f};
    float lrow[2] = {0.f, 0.f};
    float oacc[8][4];
#pragma unroll
    for (int i = 0; i < 8; i++)
#pragma unroll
        for (int j = 0; j < 4; j++) oacc[i][j] = 0.f;

    for (int kt = 0; kt < 4; kt++) {
        __syncthreads();
        for (int i = tid; i < 1024; i += 256) {
            int r = i >> 3, cs = i & 7;
            *(uint4*)(Ks + r * FLD + cs * 8) = *(const uint4*)(Kg + (kt * 128 + r) * 64 + cs * 8);
            *(uint4*)(Vs + r * FLD + cs * 8) = *(const uint4*)(Vg + (kt * 128 + r) * 64 + cs * 8);
        }
        if (tid < 128) mf[tid] = (mask[b * SEQ + kt * 128 + tid] == 0) ? 1.f : 0.f;
        __syncthreads();

        float s[16][4];
#pragma unroll
        for (int f = 0; f < 16; f++)
#pragma unroll
            for (int i = 0; i < 4; i++) s[f][i] = 0.f;

#pragma unroll
        for (int kb = 0; kb < 4; kb++) {
#pragma unroll
            for (int nb2 = 0; nb2 < 8; nb2++) {
                uint32_t bf[4];
                int krow = nb2 * 16 + (lane & 7) + ((lane >> 4) & 1) * 8;
                int kcol = kb * 16 + ((lane >> 3) & 1) * 8;
                LDSM4(bf, smem_u32(Ks + krow * FLD + kcol));
                MMA16816(s[2 * nb2],     qf[kb], bf[0], bf[1]);
                MMA16816(s[2 * nb2 + 1], qf[kb], bf[2], bf[3]);
            }
        }

#pragma unroll
        for (int f = 0; f < 16; f++) {
            int c0 = f * 8 + (lane & 3) * 2;
            float f0 = mf[c0], f1 = mf[c0 + 1];
            s[f][0] = (f0 != 0.f) ? -1e9f : s[f][0] * 0.125f;
            s[f][1] = (f1 != 0.f) ? -1e9f : s[f][1] * 0.125f;
            s[f][2] = (f0 != 0.f) ? -1e9f : s[f][2] * 0.125f;
            s[f][3] = (f1 != 0.f) ? -1e9f : s[f][3] * 0.125f;
        }

        float mx0 = -1e30f, mx1 = -1e30f;
#pragma unroll
        for (int f = 0; f < 16; f++) {
            mx0 = fmaxf(mx0, fmaxf(s[f][0], s[f][1]));
            mx1 = fmaxf(mx1, fmaxf(s[f][2], s[f][3]));
        }
        mx0 = fmaxf(mx0, __shfl_xor_sync(0xffffffffu, mx0, 1));
        mx0 = fmaxf(mx0, __shfl_xor_sync(0xffffffffu, mx0, 2));
        mx1 = fmaxf(mx1, __shfl_xor_sync(0xffffffffu, mx1, 1));
        mx1 = fmaxf(mx1, __shfl_xor_sync(0xffffffffu, mx1, 2));

        float Mn0 = fmaxf(mrow[0], mx0), Mn1 = fmaxf(mrow[1], mx1);
        float sc0 = __expf(mrow[0] - Mn0), sc1 = __expf(mrow[1] - Mn1);
        mrow[0] = Mn0; mrow[1] = Mn1;

        float rs0 = 0.f, rs1 = 0.f;
#pragma unroll
        for (int f = 0; f < 16; f++) {
            s[f][0] = __expf(s[f][0] - Mn0); s[f][1] = __expf(s[f][1] - Mn0);
            s[f][2] = __expf(s[f][2] - Mn1); s[f][3] = __expf(s[f][3] - Mn1);
            rs0 += s[f][0] + s[f][1];
            rs1 += s[f][2] + s[f][3];
        }
        rs0 += __shfl_xor_sync(0xffffffffu, rs0, 1);
        rs0 += __shfl_xor_sync(0xffffffffu, rs0, 2);
        rs1 += __shfl_xor_sync(0xffffffffu, rs1, 1);
        rs1 += __shfl_xor_sync(0xffffffffu, rs1, 2);
        lrow[0] = lrow[0] * sc0 + rs0;
        lrow[1] = lrow[1] * sc1 + rs1;

#pragma unroll
        for (int nb = 0; nb < 8; nb++) {
            oacc[nb][0] *= sc0; oacc[nb][1] *= sc0;
            oacc[nb][2] *= sc1; oacc[nb][3] *= sc1;
        }

#pragma unroll
        for (int kb = 0; kb < 8; kb++) {
            uint32_t a[4];
            a[0] = packh2(s[2 * kb][0],     s[2 * kb][1]);
            a[1] = packh2(s[2 * kb][2],     s[2 * kb][3]);
            a[2] = packh2(s[2 * kb + 1][0], s[2 * kb + 1][1]);
            a[3] = packh2(s[2 * kb + 1][2], s[2 * kb + 1][3]);
#pragma unroll
            for (int nb2 = 0; nb2 < 4; nb2++) {
                uint32_t vf[4];
                int srow = kb * 16 + (lane & 15);
                int dcol = nb2 * 16 + (lane >> 4) * 8;
                LDSM4T(vf, smem_u32(Vs + srow * FLD + dcol));
                MMA16816(oacc[2 * nb2],     a, vf[0], vf[1]);
                MMA16816(oacc[2 * nb2 + 1], a, vf[2], vf[3]);
            }
        }
    }

    float inv0 = 1.f / lrow[0], inv1 = 1.f / lrow[1];
    int r0 = qt * 128 + m0 + (lane >> 2);
#pragma unroll
    for (int nb = 0; nb < 8; nb++) {
        int c = hd * 64 + nb * 8 + (lane & 3) * 2;
        *(__half2*)(out + (size_t)(b * SEQ + r0) * DMODEL + c) =
            __floats2half2_rn(oacc[nb][0] * inv0, oacc[nb][1] * inv0);
        *(__half2*)(out + (size_t)(b * SEQ + r0 + 8) * DMODEL + c) =
            __floats2half2_rn(oacc[nb][2] * inv1, oacc[nb][3] * inv1);
    }
}

// ---------------------------------------------------------------------------
// ALL weight conversions in one launch.
// ---------------------------------------------------------------------------
__global__ void wconv_all(const float* __restrict__ sw, const float* __restrict__ tw,
                          const float* __restrict__ fw, const float* __restrict__ aw,
                          const float* __restrict__ w1, const float* __restrict__ w2,
                          half_t* __restrict__ wt, int nlayers)
{
    __shared__ float t[32][33];
    int uid = blockIdx.z;
    const float* src;
    size_t dsto;
    int Ns, Kd;
    int A = 10 + 4 * nlayers;
    int Bu = A + 4 * nlayers;

    if (uid < 6) {
        src = (uid < 3) ? (sw + (size_t)uid * DDC) : (tw + (size_t)(uid - 3) * DDC);
        dsto = OFF_ST + (size_t)uid * M1; Ns = 1024; Kd = 1024;
    } else if (uid == 6) {
        src = sw + 3 * (size_t)DDC; dsto = OFF_SW3; Ns = 1024; Kd = 1024;
    } else if (uid == 7) {
        src = tw + 3 * (size_t)DDC; dsto = OFF_TW3; Ns = 1024; Kd = 1024;
    } else if (uid < 10) {
        int c = uid - 8;
        src = fw + (size_t)c * 1024 * 1024; dsto = OFF_FW + (size_t)c * 1024;
        Ns = 1024; Kd = 2048;
    } else if (uid < A) {
        int j = uid - 10;
        src = aw + (size_t)j * DDC; dsto = OFF_AW + (size_t)j * M1; Ns = 1024; Kd = 1024;
    } else if (uid < Bu) {
        int tix = uid - A; int i = tix >> 2, c = tix & 3;
        src = w1 + (size_t)i * 4 * M1 + (size_t)c * 1024;
        dsto = OFF_W1 + (size_t)i * 4 * M1 + (size_t)c * M1;
        Ns = 4096; Kd = 1024;
    } else {
        int tix = uid - Bu; int i = tix >> 2, c = tix & 3;
        src = w2 + (size_t)i * 4 * M1 + (size_t)c * M1;
        dsto = OFF_W2 + (size_t)i * 4 * M1 + (size_t)c * 1024;
        Ns = 1024; Kd = 4096;
    }

    int n0 = blockIdx.x * 32, k0 = blockIdx.y * 32;
    int tx = threadIdx.x & 31, ty = threadIdx.x >> 5;
    for (int r = ty; r < 32; r += 8) t[r][tx] = src[(size_t)(k0 + r) * Ns + n0 + tx];
    __syncthreads();
    for (int r = ty; r < 32; r += 8)
        wt[dsto + (size_t)(n0 + r) * Kd + k0 + tx] = __float2half_rn(t[tx][r]);
}

__global__ void aconv_kernel(const float* __restrict__ x, half_t* o, int n)
{
    int i = (blockIdx.x * blockDim.x + threadIdx.x) * 4;
    if (i >= n) return;
    float4 v = *(const float4*)(x + i);
    *(__half2*)(o + i)     = __floats2half2_rn(v.x, v.y);
    *(__half2*)(o + i + 2) = __floats2half2_rn(v.z, v.w);
}

// ---------------------------------------------------------------------------
// Merged spatial+temporal attention (unchanged).
// ---------------------------------------------------------------------------
#define SP68 68
#define SMEM_STA 34816

__global__ __launch_bounds__(256)
void st_attn(const half_t* __restrict__ q, const half_t* __restrict__ k,
             const half_t* __restrict__ v,
             const half_t* __restrict__ t1, const half_t* __restrict__ t2,
             const half_t* __restrict__ t3,
             const int* __restrict__ mask,
             half_t* __restrict__ osp, half_t* __restrict__ ote)
{
    extern __shared__ float S[];
    int tid = threadIdx.x;

    if (blockIdx.x < 2048) {
        int unit = tid >> 6, tu = tid & 63;
        int u = blockIdx.x * 4 + unit;
        int h = u & 15;
        int c = (u >> 4) & 63;
        int b = u >> 10;
        int tb = b * SEQ + c * 8;
        float* Qs = S + unit * 1696;
        float* Ks = Qs + 544;
        float* Vs = Ks + 544;
        float* Ps = Vs + 544;

        {
            int r = tu >> 3, d0 = (tu & 7) * 8;
            size_t g = (size_t)(tb + r) * DMODEL + h * DKH + d0;
            uint4 qv = *(const uint4*)(q + g);
            uint4 kv = *(const uint4*)(k + g);
            uint4 vv = *(const uint4*)(v + g);
            const __half2* qh = (const __half2*)&qv;
            const __half2* kh = (const __half2*)&kv;
            const __half2* vh = (const __half2*)&vv;
#pragma unroll
            for (int j = 0; j < 4; j++) {
                float2 f = __half22float2(qh[j]);
                Qs[r * SP68 + d0 + 2 * j] = f.x; Qs[r * SP68 + d0 + 2 * j + 1] = f.y;
                f = __half22float2(kh[j]);
                Ks[r * SP68 + d0 + 2 * j] = f.x; Ks[r * SP68 + d0 + 2 * j + 1] = f.y;
                f = __half22float2(vh[j]);
                Vs[r * SP68 + d0 + 2 * j] = f.x; Vs[r * SP68 + d0 + 2 * j + 1] = f.y;
            }
        }
        __syncthreads();

        int i = tu >> 3, j = tu & 7;
        float4 a4; a4.x = 0.f; a4.y = 0.f; a4.z = 0.f; a4.w = 0.f;
#pragma unroll
        for (int d = 0; d < 64; d += 4) {
            float4 qa = *(const float4*)&Qs[i * SP68 + d];
            float4 kb = *(const float4*)&Ks[j * SP68 + d];
            a4.x += qa.x * kb.x; a4.y += qa.y * kb.y;
            a4.z += qa.z * kb.z; a4.w += qa.w * kb.w;
        }
        float s = (a4.x + a4.y + a4.z + a4.w) * 0.125f;
        if (mask[b * SEQ + c * 8 + j] == 0) s = -1e9f;

        float m = s;
        m = fmaxf(m, __shfl_xor_sync(0xffffffffu, m, 1));
        m = fmaxf(m, __shfl_xor_sync(0xffffffffu, m, 2));
        m = fmaxf(m, __shfl_xor_sync(0xffffffffu, m, 4));
        float p = expf(s - m);
        float sum = p;
        sum += __shfl_xor_sync(0xffffffffu, sum, 1);
        sum += __shfl_xor_sync(0xffffffffu, sum, 2);
        sum += __shfl_xor_sync(0xffffffffu, sum, 4);
        Ps[i * 8 + j] = p / sum;
        __syncthreads();

        {
            int r = tu >> 3, d0 = (tu & 7) * 8;
            float4 o0, o1;
            o0.x = o0.y = o0.z = o0.w = 0.f;
            o1.x = o1.y = o1.z = o1.w = 0.f;
#pragma unroll
            for (int jj = 0; jj < 8; jj++) {
                float pv = Ps[r * 8 + jj];
                float4 v0 = *(const float4*)&Vs[jj * SP68 + d0];
                float4 v1 = *(const float4*)&Vs[jj * SP68 + d0 + 4];
                o0.x += pv * v0.x; o0.y += pv * v0.y; o0.z += pv * v0.z; o0.w += pv * v0.w;
                o1.x += pv * v1.x; o1.y += pv * v1.y; o1.z += pv * v1.z; o1.w += pv * v1.w;
            }
            uint4 ov;
            ((uint32_t*)&ov)[0] = packh2(o0.x, o0.y);
            ((uint32_t*)&ov)[1] = packh2(o0.z, o0.w);
            ((uint32_t*)&ov)[2] = packh2(o1.x, o1.y);
            ((uint32_t*)&ov)[3] = packh2(o1.z, o1.w);
            *(uint4*)(osp + (size_t)(tb + r) * DMODEL + h * DKH + d0) = ov;
        }
    } else {
        int u = blockIdx.x - 2048;
        int h = u & 15;
        int jpos = (u >> 4) & 7;
        int b = u >> 7;
        int tx = tid & 15, ty = tid >> 4;
        half_t* QVh  = (half_t*)S;
        half_t* Ks2h = QVh + 64 * SP68;
        float*  Pst  = (float*)(Ks2h + 64 * SP68);

        for (int idx = tid; idx < 1024; idx += 256) {
            int r = idx >> 4;
            int d0 = (idx & 15) << 2;
            size_t g = (size_t)(b * SEQ + r * 8 + jpos) * DMODEL + h * DKH + d0;
            uint2 av = *(const uint2*)(t1 + g);
            const half_t* ah = (const half_t*)&av;
            QVh[(d0 + 0) * SP68 + r] = ah[0];
            QVh[(d0 + 1) * SP68 + r] = ah[1];
            QVh[(d0 + 2) * SP68 + r] = ah[2];
            QVh[(d0 + 3) * SP68 + r] = ah[3];
            uint2 kv = *(const uint2*)(t2 + g);
            const half_t* kh = (const half_t*)&kv;
            Ks2h[(d0 + 0) * SP68 + r] = kh[0];
            Ks2h[(d0 + 1) * SP68 + r] = kh[1];
            Ks2h[(d0 + 2) * SP68 + r] = kh[2];
            Ks2h[(d0 + 3) * SP68 + r] = kh[3];
        }
        __syncthreads();

        float acc[4][4];
#pragma unroll
        for (int i = 0; i < 4; i++)
#pragma unroll
            for (int j = 0; j < 4; j++) acc[i][j] = 0.f;

        for (int d = 0; d < 64; d++) {
            uint2 au = *(const uint2*)&QVh[d * SP68 + ty * 4];
            uint2 bu = *(const uint2*)&Ks2h[d * SP68 + tx * 4];
            const __half2* ah = (const __half2*)&au;
            const __half2* bh = (const __half2*)&bu;
            float2 a01 = __half22float2(ah[0]), a23 = __half22float2(ah[1]);
            float2 b01 = __half22float2(bh[0]), b23 = __half22float2(bh[1]);
            float av[4] = {a01.x, a01.y, a23.x, a23.y};
            float bv[4] = {b01.x, b01.y, b23.x, b23.y};
#pragma unroll
            for (int i = 0; i < 4; i++)
#pragma unroll
                for (int j = 0; j < 4; j++) acc[i][j] += av[i] * bv[j];
        }
#pragma unroll
        for (int jj = 0; jj < 4; jj++) {
            int cc = tx * 4 + jj;
            bool msk = (mask[b * SEQ + cc * 8 + jpos] == 0);
#pragma unroll
            for (int i = 0; i < 4; i++)
                Pst[cc * SP68 + ty * 4 + i] = msk ? -1e9f : acc[i][jj] * 0.125f;
        }
        __syncthreads();

        if (tid < 64) {
            float m = -1e30f;
            for (int cc = 0; cc < 64; cc++) m = fmaxf(m, Pst[cc * SP68 + tid]);
            float sum = 0.f;
            for (int cc = 0; cc < 64; cc++) {
                float p = expf(Pst[cc * SP68 + tid] - m);
                Pst[cc * SP68 + tid] = p; sum += p;
            }
            float inv = 1.f / sum;
            for (int cc = 0; cc < 64; cc++) Pst[cc * SP68 + tid] *= inv;
        }
        __syncthreads();

        for (int idx = tid; idx < 1024; idx += 256) {
            int r = idx >> 4;
            int d0 = (idx & 15) << 2;
            size_t g = (size_t)(b * SEQ + r * 8 + jpos) * DMODEL + h * DKH + d0;
            *(uint2*)&QVh[r * SP68 + d0] = *(const uint2*)(t3 + g);
        }
        __syncthreads();

        float oacc[4][4];
#pragma unroll
        for (int i = 0; i < 4; i++)
#pragma unroll
            for (int j = 0; j < 4; j++) oacc[i][j] = 0.f;

        for (int kk = 0; kk < 64; kk++) {
            float4 av4 = *(const float4*)&Pst[kk * SP68 + ty * 4];
            uint2 bu = *(const uint2*)&QVh[kk * SP68 + tx * 4];
            const __half2* bh = (const __half2*)&bu;
            float2 b01 = __half22float2(bh[0]), b23 = __half22float2(bh[1]);
            float av[4] = {av4.x, av4.y, av4.z, av4.w};
            float bv[4] = {b01.x, b01.y, b23.x, b23.y};
#pragma unroll
            for (int i = 0; i < 4; i++)
#pragma unroll
                for (int j = 0; j < 4; j++) oacc[i][j] += av[i] * bv[j];
        }
#pragma unroll
        for (int i = 0; i < 4; i++) {
            uint2 ov;
            ((uint32_t*)&ov)[0] = packh2(oacc[i][0], oacc[i][1]);
            ((uint32_t*)&ov)[1] = packh2(oacc[i][2], oacc[i][3]);
            *(uint2*)(ote + (size_t)(b * SEQ + (ty * 4 + i) * 8 + jpos) * DMODEL +
                      h * DKH + tx * 4) = ov;
        }
    }
}

// ---------------------------------------------------------------------------
// LayerNorm: warp-per-row, 8 rows per 256-thread block.
// ---------------------------------------------------------------------------
__global__ __launch_bounds__(256)
void layernorm_kernel(const float* __restrict__ x,
                      const float* __restrict__ gamma,
                      const float* __restrict__ beta,
                      half_t* __restrict__ oh)
{
    int row = blockIdx.x * 8 + (threadIdx.x >> 5);
    int lane = threadIdx.x & 31;
    const float* xr = x + (size_t)row * DMODEL;

    float4 v[8];
    float s1 = 0.f, s2 = 0.f;
#pragma unroll
    for (int i = 0; i < 8; i++) {
        v[i] = *(const float4*)(xr + lane * 4 + i * 128);
        s1 += v[i].x + v[i].y + v[i].z + v[i].w;
        s2 += v[i].x * v[i].x + v[i].y * v[i].y + v[i].z * v[i].z + v[i].w * v[i].w;
    }
#pragma unroll
    for (int o = 16; o; o >>= 1) {
        s1 += __shfl_xor_sync(0xffffffffu, s1, o);
        s2 += __shfl_xor_sync(0xffffffffu, s2, o);
    }
    float mean = s1 * (1.f / DMODEL);
    float var = s2 * (1.f / DMODEL) - mean * mean;
    float inv = rsqrtf(var + LN_EPS);

#pragma unroll
    for (int i = 0; i < 8; i++) {
        int c = lane * 4 + i * 128;
        float4 g = *(const float4*)(gamma + c);
        float4 bb = *(const float4*)(beta + c);
        uint2 ov;
        ((uint32_t*)&ov)[0] = packh2((v[i].x - mean) * inv * g.x + bb.x,
                                     (v[i].y - mean) * inv * g.y + bb.y);
        ((uint32_t*)&ov)[1] = packh2((v[i].z - mean) * inv * g.z + bb.z,
                                     (v[i].w - mean) * inv * g.w + bb.w);
        *(uint2*)(oh + (size_t)row * DMODEL + c) = ov;
    }
}

// ---------------------------------------------------------------------------
// Host orchestration
// ---------------------------------------------------------------------------
static inline int capgrid(int tiles) { return tiles < GEMM_MAXGRID ? tiles : GEMM_MAXGRID; }

extern "C" void kernel_launch(void* const* d_in, const int* in_sizes, int n_in,
                              void* d_out, int out_size)
{
    (void)n_in; (void)out_size;
    const float* x    = (const float*)d_in[0];
    const int*   mask = (const int*)  d_in[1];
    const float* sw   = (const float*)d_in[2];
    const float* sb   = (const float*)d_in[3];
    const float* tw   = (const float*)d_in[4];
    const float* tbia = (const float*)d_in[5];
    const float* fw   = (const float*)d_in[6];
    const float* fb   = (const float*)d_in[7];
    const float* aw   = (const float*)d_in[8];
    const float* ab   = (const float*)d_in[9];
    const float* w1   = (const float*)d_in[10];
    const float* b1   = (const float*)d_in[11];
    const float* w2   = (const float*)d_in[12];
    const float* b2   = (const float*)d_in[13];
    const float* lns  = (const float*)d_in[14];
    const float* lnb  = (const float*)d_in[15];
    float* out = (float*)d_out;

    cudaFuncSetAttribute(gemm_hmma<0>, cudaFuncAttributeMaxDynamicSharedMemorySize, SMEM_GEMM);
    cudaFuncSetAttribute(gemm_hmma<1>, cudaFuncAttributeMaxDynamicSharedMemorySize, SMEM_GEMM);
    cudaFuncSetAttribute(gemm_hmma<2>, cudaFuncAttributeMaxDynamicSharedMemorySize, SMEM_GEMM);
    cudaFuncSetAttribute(gemm_hmma<3>, cudaFuncAttributeMaxDynamicSharedMemorySize, SMEM_GEMM);
    cudaFuncSetAttribute(flash_attn,   cudaFuncAttributeMaxDynamicSharedMemorySize, SMEM_FLASH);
    cudaFuncSetAttribute(st_attn,      cudaFuncAttributeMaxDynamicSharedMemorySize, SMEM_STA);

    half_t *wt, *xh, *hh, *ah, *fh, *qkvh, *q, *k, *v, *t1, *t2, *t3;
    float *xb;
    cudaGetSymbolAddress((void**)&wt,   g_wt);
    cudaGetSymbolAddress((void**)&xh,   g_xh);
    cudaGetSymbolAddress((void**)&hh,   g_hh);
    cudaGetSymbolAddress((void**)&ah,   g_ah);
    cudaGetSymbolAddress((void**)&fh,   g_fh);
    cudaGetSymbolAddress((void**)&qkvh, g_qkvh);
    cudaGetSymbolAddress((void**)&q,    g_q);
    cudaGetSymbolAddress((void**)&k,    g_k);
    cudaGetSymbolAddress((void**)&v,    g_v);
    cudaGetSymbolAddress((void**)&t1,   g_t1);
    cudaGetSymbolAddress((void**)&t2,   g_t2);
    cudaGetSymbolAddress((void**)&t3,   g_t3);
    cudaGetSymbolAddress((void**)&xb,   g_xb);

    const size_t DD = (size_t)DMODEL * DMODEL;
    int nlayers = in_sizes[8] / (int)(4 * DD);

    wconv_all<<<dim3(32, 32, 10 + 12 * nlayers), 256>>>(sw, tw, fw, aw, w1, w2, wt, nlayers);
    aconv_kernel<<<(MTOK * DMODEL / 4 + 255) / 256, 256>>>(x, xh, MTOK * DMODEL);

    // spatial+temporal QKV: N=6144 -> 48x32 = 1536 tiles, persistent grid
    gemm_hmma<2><<<capgrid(48 * 32), 256, SMEM_GEMM>>>(
        xh, wt + OFF_ST, nullptr, nullptr, sb, tbia, nullptr, nullptr, nullptr,
        MTOK, 6144, DMODEL, 0, 0, 48, q, k, v, t1, t2, t3);

    st_attn<<<3072, 256, SMEM_STA>>>(q, k, v, t1, t2, t3, mask, ah, hh);

    gemm_hmma<3><<<dim3(capgrid(8 * 32), 1, 2), 256, SMEM_GEMM>>>(
        ah, wt + OFF_SW3, hh, wt + OFF_TW3, sb + 3 * DMODEL, tbia + 3 * DMODEL,
        nullptr, nullptr, fh, MTOK, DMODEL, DMODEL, 0, 2048, 8,
        nullptr, nullptr, nullptr, nullptr, nullptr, nullptr);

    gemm_hmma<0><<<capgrid(8 * 32), 256, SMEM_GEMM>>>(
        fh, wt + OFF_FW, nullptr, nullptr, fb, nullptr, nullptr, xb, nullptr,
        MTOK, DMODEL, 2 * DMODEL, 0, DMODEL, 8,
        nullptr, nullptr, nullptr, nullptr, nullptr, nullptr);

    for (int i = 0; i < nlayers; i++) {
        const float* abi = ab + (size_t)i * 4 * DMODEL;
        const half_t* awi = wt + OFF_AW + (size_t)i * 4 * M1;

        layernorm_kernel<<<MTOK / 8, 256>>>(xb, lns + (i * 2 + 0) * DMODEL,
                                            lnb + (i * 2 + 0) * DMODEL, hh);
        gemm_hmma<1><<<capgrid(24 * 32), 256, SMEM_GEMM>>>(
            hh, awi, nullptr, nullptr, abi, nullptr, nullptr, nullptr, qkvh,
            MTOK, 3 * DMODEL, DMODEL, 0, 0, 24,
            nullptr, nullptr, nullptr, nullptr, nullptr, nullptr);

        flash_attn<<<dim3(4, 128), 256, SMEM_FLASH>>>(qkvh, mask, ah);

        gemm_hmma<0><<<capgrid(8 * 32), 256, SMEM_GEMM>>>(
            ah, awi + 3 * M1, nullptr, nullptr, abi + 3 * DMODEL, nullptr, xb, xb, nullptr,
            MTOK, DMODEL, DMODEL, 0, DMODEL, 8,
            nullptr, nullptr, nullptr, nullptr, nullptr, nullptr);

        layernorm_kernel<<<MTOK / 8, 256>>>(xb, lns + (i * 2 + 1) * DMODEL,
                                            lnb + (i * 2 + 1) * DMODEL, hh);
        gemm_hmma<0><<<capgrid(32 * 32), 256, SMEM_GEMM>>>(
            hh, wt + OFF_W1 + (size_t)i * 4 * M1, nullptr, nullptr, b1 + i * DFF, nullptr,
            nullptr, nullptr, fh, MTOK, DFF, DMODEL, 1, DFF, 32,
            nullptr, nullptr, nullptr, nullptr, nullptr, nullptr);
        float* dst = (i == nlayers - 1) ? out : xb;
        gemm_hmma<0><<<capgrid(8 * 32), 256, SMEM_GEMM>>>(
            fh, wt + OFF_W2 + (size_t)i * 4 * M1, nullptr, nullptr, b2 + i * DMODEL, nullptr,
            xb, dst, nullptr, MTOK, DMODEL, DFF, 0, DMODEL, 8,
            nullptr, nullptr, nullptr, nullptr, nullptr, nullptr);
    }
}

// round 10
// speedup vs baseline: 1.0431x; 1.0431x over previous
#include <cuda_runtime.h>
#include <cuda_fp16.h>
#include <cstdint>
#include <math.h>

#define DMODEL 1024
#define BATCH  8
#define SEQ    512
#define NHEAD  16
#define DKH    64
#define MTOK   4096
#define DFF    4096
#define NCLIP  64
#define LN_EPS 1e-5f

typedef __half half_t;

// ---------------------------------------------------------------------------
// PTX helpers (arch-agnostic: mma.sync / ldmatrix / cp.async only)
// ---------------------------------------------------------------------------
__device__ __forceinline__ uint32_t smem_u32(const void* p) {
    uint32_t a;
    asm("{ .reg .u64 t; cvta.to.shared.u64 t, %1; cvt.u32.u64 %0, t; }" : "=r"(a) : "l"(p));
    return a;
}

#define LDSM4(r, a) \
    asm volatile("ldmatrix.sync.aligned.m8n8.x4.shared.b16 {%0,%1,%2,%3}, [%4];" \
        : "=r"((r)[0]), "=r"((r)[1]), "=r"((r)[2]), "=r"((r)[3]) : "r"(a))

#define LDSM4T(r, a) \
    asm volatile("ldmatrix.sync.aligned.m8n8.x4.trans.shared.b16 {%0,%1,%2,%3}, [%4];" \
        : "=r"((r)[0]), "=r"((r)[1]), "=r"((r)[2]), "=r"((r)[3]) : "r"(a))

#define MMA16816(c, a, b0, b1) \
    asm volatile("mma.sync.aligned.m16n8k16.row.col.f32.f16.f16.f32 " \
        "{%0,%1,%2,%3}, {%4,%5,%6,%7}, {%8,%9}, {%0,%1,%2,%3};" \
        : "+f"((c)[0]), "+f"((c)[1]), "+f"((c)[2]), "+f"((c)[3]) \
        : "r"((a)[0]), "r"((a)[1]), "r"((a)[2]), "r"((a)[3]), "r"(b0), "r"(b1))

#define CPASYNC16(d, s) asm volatile("cp.async.cg.shared.global [%0], [%1], 16;" :: "r"(d), "l"(s))
#define CPCOMMIT()      asm volatile("cp.async.commit_group;" ::: "memory")
#define CPWAIT(n)       asm volatile("cp.async.wait_group %0;" :: "n"(n) : "memory")

__device__ __forceinline__ uint32_t packh2(float x, float y) {
    __half2 h = __floats2half2_rn(x, y);
    return *(uint32_t*)&h;
}

// ---------------------------------------------------------------------------
// Device scratch
// ---------------------------------------------------------------------------
#define WT_TOT (34u * 1024u * 1024u)
__device__ half_t g_wt[WT_TOT];
__device__ half_t g_xh[MTOK * DMODEL];
__device__ half_t g_hh[MTOK * DMODEL];
__device__ half_t g_ah[MTOK * DMODEL];
__device__ half_t g_fh[MTOK * DFF];
__device__ half_t g_qkvh[3 * 128 * SEQ * DKH];
__device__ half_t g_q[MTOK * DMODEL];
__device__ half_t g_k[MTOK * DMODEL];
__device__ half_t g_v[MTOK * DMODEL];
__device__ half_t g_t1[MTOK * DMODEL];
__device__ half_t g_t2[MTOK * DMODEL];
__device__ half_t g_t3[MTOK * DMODEL];
__device__ float  g_xb[MTOK * DMODEL];

// weight offsets (units of 1M elements) inside g_wt
#define M1 (1024u * 1024u)
#define DDC (1024u * 1024u)
#define OFF_ST  0u
#define OFF_SW3 (6u * M1)
#define OFF_TW3 (7u * M1)
#define OFF_FW  (8u * M1)
#define OFF_AW  (10u * M1)
#define OFF_W1  (18u * M1)
#define OFF_W2  (26u * M1)

// ---------------------------------------------------------------------------
// fp16 HMMA GEMM, BK=64 (128B rows, 3-bit XOR swizzle), 3-stage cp.async.
// 2 CTAs/SM via launch_bounds. Non-persistent grid (R9 persistent loop
// regressed: pipeline-refill cost > wave-tail savings).
// MODE 0: standard; MODE 1: QKV head-major scatter;
// MODE 2: six fp16 buffers by col/1024; MODE 3: z-batched out-proj.
// ---------------------------------------------------------------------------
#define STAGES 3
#define STAGE_BYTES 32768
#define SMEM_GEMM (STAGES * STAGE_BYTES)

template<int MODE>
__global__ __launch_bounds__(256, 2)
void gemm_hmma(const half_t* __restrict__ A, const half_t* __restrict__ B,
               const half_t* __restrict__ A2, const half_t* __restrict__ B2,
               const float* __restrict__ bias, const float* __restrict__ bias2,
               const float* __restrict__ R, float* Cf, half_t* Ch,
               int M, int N, int K, int relu, int ldC,
               half_t* q0, half_t* q1, half_t* q2, half_t* q3, half_t* q4, half_t* q5)
{
    extern __shared__ char smem[];
    uint32_t sb = smem_u32(smem);
    const int tid = threadIdx.x;
    const int lane = tid & 31, warp = tid >> 5;
    const int row0 = blockIdx.y * 128, col0 = blockIdx.x * 128;
    const int wm = (warp >> 2) * 64;
    const int wn = (warp & 3) * 32;

    if (MODE == 3 && blockIdx.z == 1) { A = A2; B = B2; bias = bias2; }

    int segr[4], segc[4];
#pragma unroll
    for (int i = 0; i < 4; i++) { int s = tid + i * 256; segr[i] = s >> 3; segc[i] = s & 7; }

    int rA[4], swA[4];
#pragma unroll
    for (int mt = 0; mt < 4; mt++) {
        int r = wm + mt * 16 + (lane & 15);
        rA[mt] = r; swA[mt] = r & 7;
    }
    int rB[2], swB[2];
#pragma unroll
    for (int n2 = 0; n2 < 2; n2++) {
        int r = wn + n2 * 16 + (lane & 7) + ((lane >> 4) << 3);
        rB[n2] = r; swB[n2] = r & 7;
    }
    const int csA = lane >> 4;
    const int csB = (lane >> 3) & 1;

    float acc[4][4][4];
#pragma unroll
    for (int mt = 0; mt < 4; mt++)
#pragma unroll
        for (int nt = 0; nt < 4; nt++)
#pragma unroll
            for (int i = 0; i < 4; i++) acc[mt][nt][i] = 0.f;

    const int NT = K >> 6;

#define GISSUE(kt, st) do { \
    uint32_t sA_ = sb + (st) * STAGE_BYTES; \
    uint32_t sB_ = sA_ + 16384; \
    _Pragma("unroll") for (int i = 0; i < 4; i++) { \
        int r_ = segr[i], c_ = segc[i]; \
        uint32_t sw_ = (uint32_t)((c_ ^ (r_ & 7)) << 4); \
        CPASYNC16(sA_ + r_ * 128 + sw_, A + (size_t)(row0 + r_) * K + (size_t)(kt) * 64 + c_ * 8); \
        CPASYNC16(sB_ + r_ * 128 + sw_, B + (size_t)(col0 + r_) * K + (size_t)(kt) * 64 + c_ * 8); \
    } \
    CPCOMMIT(); } while (0)

    GISSUE(0, 0);
    GISSUE(1, 1);

    for (int kt = 0; kt < NT; kt++) {
        if (kt == NT - 1) { CPWAIT(0); } else { CPWAIT(1); }
        __syncthreads();
        if (kt + 2 < NT) GISSUE(kt + 2, (kt + 2) % 3);

        uint32_t sA = sb + (kt % 3) * STAGE_BYTES;
        uint32_t sB = sA + 16384;
#pragma unroll
        for (int k16 = 0; k16 < 4; k16++) {
            uint32_t ra[4][4], rb[2][4];
#pragma unroll
            for (int mt = 0; mt < 4; mt++)
                LDSM4(ra[mt], sA + rA[mt] * 128 + ((((k16 << 1) + csA) ^ swA[mt]) << 4));
#pragma unroll
            for (int n2 = 0; n2 < 2; n2++)
                LDSM4(rb[n2], sB + rB[n2] * 128 + ((((k16 << 1) + csB) ^ swB[n2]) << 4));
#pragma unroll
            for (int mt = 0; mt < 4; mt++)
#pragma unroll
                for (int nt = 0; nt < 4; nt++)
                    MMA16816(acc[mt][nt], ra[mt],
                             rb[nt >> 1][(nt & 1) * 2], rb[nt >> 1][(nt & 1) * 2 + 1]);
        }
    }

    // Epilogue
    half_t* obuf = nullptr;
    if (MODE == 2) {
        int bsel = col0 >> 10;
        obuf = (bsel == 0) ? q0 : (bsel == 1) ? q1 : (bsel == 2) ? q2 :
               (bsel == 3) ? q3 : (bsel == 4) ? q4 : q5;
    }
    const int cbase = (MODE == 3) ? (int)blockIdx.z * 1024 : 0;
#pragma unroll
    for (int mt = 0; mt < 4; mt++) {
        int rg = row0 + wm + mt * 16 + (lane >> 2);
#pragma unroll
        for (int nt = 0; nt < 4; nt++) {
            int c = col0 + wn + nt * 8 + (lane & 3) * 2;
            float* a = acc[mt][nt];
#pragma unroll
            for (int h = 0; h < 2; h++) {
                int row = rg + h * 8;
                float v0 = a[h * 2], v1 = a[h * 2 + 1];
                if (MODE == 0) {
                    if (bias) { v0 += bias[c]; v1 += bias[c + 1]; }
                    if (R) {
                        float2 rr = *(const float2*)(R + (size_t)row * N + c);
                        v0 += rr.x; v1 += rr.y;
                    }
                    if (relu) { v0 = fmaxf(v0, 0.f); v1 = fmaxf(v1, 0.f); }
                    if (Cf) {
                        float2 o; o.x = v0; o.y = v1;
                        *(float2*)(Cf + (size_t)row * ldC + c) = o;
                    }
                    if (Ch)
                        *(__half2*)(Ch + (size_t)row * ldC + c) = __floats2half2_rn(v0, v1);
                } else if (MODE == 1) {
                    v0 += bias[c]; v1 += bias[c + 1];
                    int qkv = c >> 10, hh_ = (c >> 6) & 15, d = c & 63;
                    int b = row >> 9, srow = row & 511;
                    size_t dst = (((size_t)(qkv * 128 + b * 16 + hh_) * 512) + srow) * 64 + d;
                    *(__half2*)(Ch + dst) = __floats2half2_rn(v0, v1);
                } else if (MODE == 2) {
                    float b0v = (c < 3072) ? bias[c] : bias2[c - 3072];
                    float b1v = (c + 1 < 3072) ? bias[c + 1] : bias2[c + 1 - 3072];
                    *(__half2*)(obuf + (size_t)row * 1024 + (c & 1023)) =
                        __floats2half2_rn(v0 + b0v, v1 + b1v);
                } else { // MODE 3
                    v0 += bias[c]; v1 += bias[c + 1];
                    *(__half2*)(Ch + (size_t)row * ldC + cbase + c) = __floats2half2_rn(v0, v1);
                }
            }
        }
    }
}

// ---------------------------------------------------------------------------
// Flash attention (encoder): per (b,h) 512x512, fp16 mma, online softmax.
// ---------------------------------------------------------------------------
#define FLD 72
#define SMEM_FLASH (3 * 128 * FLD * 2 + 512)

__global__ __launch_bounds__(256)
void flash_attn(const half_t* __restrict__ qkvh, const int* __restrict__ mask,
                half_t* __restrict__ out)
{
    extern __shared__ char sm[];
    half_t* Qs = (half_t*)sm;
    half_t* Ks = Qs + 128 * FLD;
    half_t* Vs = Ks + 128 * FLD;
    float*  mf = (float*)(Vs + 128 * FLD);

    const int bh = blockIdx.y, qt = blockIdx.x;
    const int b = bh >> 4, hd = bh & 15;
    const int tid = threadIdx.x, lane = tid & 31, warp = tid >> 5;
    const int m0 = warp * 16;

    const half_t* Qg = qkvh + (((size_t)(0 * 128 + bh) * 512) + qt * 128) * 64;
    const half_t* Kg = qkvh + ((size_t)(1 * 128 + bh) * 512) * 64;
    const half_t* Vg = qkvh + ((size_t)(2 * 128 + bh) * 512) * 64;

    for (int i = tid; i < 1024; i += 256) {
        int r = i >> 3, cs = i & 7;
        *(uint4*)(Qs + r * FLD + cs * 8) = *(const uint4*)(Qg + r * 64 + cs * 8);
    }
    __syncthreads();

    uint32_t qf[4][4];
#pragma unroll
    for (int kb = 0; kb < 4; kb++)
        LDSM4(qf[kb], smem_u32(Qs + (m0 + (lane & 15)) * FLD + kb * 16 + (lane >> 4) * 8));

    float mrow[2] = {-1e30f, -1e30f};
    float lrow[2] = {0.f, 0.f};
    float oacc[8][4];
#pragma unroll
    for (int i = 0; i < 8; i++)
#pragma unroll
        for (int j = 0; j < 4; j++) oacc[i][j] = 0.f;

    for (int kt = 0; kt < 4; kt++) {
        __syncthreads();
        for (int i = tid; i < 1024; i += 256) {
            int r = i >> 3, cs = i & 7;
            *(uint4*)(Ks + r * FLD + cs * 8) = *(const uint4*)(Kg + (kt * 128 + r) * 64 + cs * 8);
            *(uint4*)(Vs + r * FLD + cs * 8) = *(const uint4*)(Vg + (kt * 128 + r) * 64 + cs * 8);
        }
        if (tid < 128) mf[tid] = (mask[b * SEQ + kt * 128 + tid] == 0) ? 1.f : 0.f;
        __syncthreads();

        float s[16][4];
#pragma unroll
        for (int f = 0; f < 16; f++)
#pragma unroll
            for (int i = 0; i < 4; i++) s[f][i] = 0.f;

#pragma unroll
        for (int kb = 0; kb < 4; kb++) {
#pragma unroll
            for (int nb2 = 0; nb2 < 8; nb2++) {
                uint32_t bf[4];
                int krow = nb2 * 16 + (lane & 7) + ((lane >> 4) & 1) * 8;
                int kcol = kb * 16 + ((lane >> 3) & 1) * 8;
                LDSM4(bf, smem_u32(Ks + krow * FLD + kcol));
                MMA16816(s[2 * nb2],     qf[kb], bf[0], bf[1]);
                MMA16816(s[2 * nb2 + 1], qf[kb], bf[2], bf[3]);
            }
        }

#pragma unroll
        for (int f = 0; f < 16; f++) {
            int c0 = f * 8 + (lane & 3) * 2;
            float f0 = mf[c0], f1 = mf[c0 + 1];
            s[f][0] = (f0 != 0.f) ? -1e9f : s[f][0] * 0.125f;
            s[f][1] = (f1 != 0.f) ? -1e9f : s[f][1] * 0.125f;
            s[f][2] = (f0 != 0.f) ? -1e9f : s[f][2] * 0.125f;
            s[f][3] = (f1 != 0.f) ? -1e9f : s[f][3] * 0.125f;
        }

        float mx0 = -1e30f, mx1 = -1e30f;
#pragma unroll
        for (int f = 0; f < 16; f++) {
            mx0 = fmaxf(mx0, fmaxf(s[f][0], s[f][1]));
            mx1 = fmaxf(mx1, fmaxf(s[f][2], s[f][3]));
        }
        mx0 = fmaxf(mx0, __shfl_xor_sync(0xffffffffu, mx0, 1));
        mx0 = fmaxf(mx0, __shfl_xor_sync(0xffffffffu, mx0, 2));
        mx1 = fmaxf(mx1, __shfl_xor_sync(0xffffffffu, mx1, 1));
        mx1 = fmaxf(mx1, __shfl_xor_sync(0xffffffffu, mx1, 2));

        float Mn0 = fmaxf(mrow[0], mx0), Mn1 = fmaxf(mrow[1], mx1);
        float sc0 = __expf(mrow[0] - Mn0), sc1 = __expf(mrow[1] - Mn1);
        mrow[0] = Mn0; mrow[1] = Mn1;

        float rs0 = 0.f, rs1 = 0.f;
#pragma unroll
        for (int f = 0; f < 16; f++) {
            s[f][0] = __expf(s[f][0] - Mn0); s[f][1] = __expf(s[f][1] - Mn0);
            s[f][2] = __expf(s[f][2] - Mn1); s[f][3] = __expf(s[f][3] - Mn1);
            rs0 += s[f][0] + s[f][1];
            rs1 += s[f][2] + s[f][3];
        }
        rs0 += __shfl_xor_sync(0xffffffffu, rs0, 1);
        rs0 += __shfl_xor_sync(0xffffffffu, rs0, 2);
        rs1 += __shfl_xor_sync(0xffffffffu, rs1, 1);
        rs1 += __shfl_xor_sync(0xffffffffu, rs1, 2);
        lrow[0] = lrow[0] * sc0 + rs0;
        lrow[1] = lrow[1] * sc1 + rs1;

#pragma unroll
        for (int nb = 0; nb < 8; nb++) {
            oacc[nb][0] *= sc0; oacc[nb][1] *= sc0;
            oacc[nb][2] *= sc1; oacc[nb][3] *= sc1;
        }

#pragma unroll
        for (int kb = 0; kb < 8; kb++) {
            uint32_t a[4];
            a[0] = packh2(s[2 * kb][0],     s[2 * kb][1]);
            a[1] = packh2(s[2 * kb][2],     s[2 * kb][3]);
            a[2] = packh2(s[2 * kb + 1][0], s[2 * kb + 1][1]);
            a[3] = packh2(s[2 * kb + 1][2], s[2 * kb + 1][3]);
#pragma unroll
            for (int nb2 = 0; nb2 < 4; nb2++) {
                uint32_t vf[4];
                int srow = kb * 16 + (lane & 15);
                int dcol = nb2 * 16 + (lane >> 4) * 8;
                LDSM4T(vf, smem_u32(Vs + srow * FLD + dcol));
                MMA16816(oacc[2 * nb2],     a, vf[0], vf[1]);
                MMA16816(oacc[2 * nb2 + 1], a, vf[2], vf[3]);
            }
        }
    }

    float inv0 = 1.f / lrow[0], inv1 = 1.f / lrow[1];
    int r0 = qt * 128 + m0 + (lane >> 2);
#pragma unroll
    for (int nb = 0; nb < 8; nb++) {
        int c = hd * 64 + nb * 8 + (lane & 3) * 2;
        *(__half2*)(out + (size_t)(b * SEQ + r0) * DMODEL + c) =
            __floats2half2_rn(oacc[nb][0] * inv0, oacc[nb][1] * inv0);
        *(__half2*)(out + (size_t)(b * SEQ + r0 + 8) * DMODEL + c) =
            __floats2half2_rn(oacc[nb][2] * inv1, oacc[nb][3] * inv1);
    }
}

// ---------------------------------------------------------------------------
// ALL weight conversions in one launch.
// ---------------------------------------------------------------------------
__global__ void wconv_all(const float* __restrict__ sw, const float* __restrict__ tw,
                          const float* __restrict__ fw, const float* __restrict__ aw,
                          const float* __restrict__ w1, const float* __restrict__ w2,
                          half_t* __restrict__ wt, int nlayers)
{
    __shared__ float t[32][33];
    int uid = blockIdx.z;
    const float* src;
    size_t dsto;
    int Ns, Kd;
    int A = 10 + 4 * nlayers;
    int Bu = A + 4 * nlayers;

    if (uid < 6) {
        src = (uid < 3) ? (sw + (size_t)uid * DDC) : (tw + (size_t)(uid - 3) * DDC);
        dsto = OFF_ST + (size_t)uid * M1; Ns = 1024; Kd = 1024;
    } else if (uid == 6) {
        src = sw + 3 * (size_t)DDC; dsto = OFF_SW3; Ns = 1024; Kd = 1024;
    } else if (uid == 7) {
        src = tw + 3 * (size_t)DDC; dsto = OFF_TW3; Ns = 1024; Kd = 1024;
    } else if (uid < 10) {
        int c = uid - 8;
        src = fw + (size_t)c * 1024 * 1024; dsto = OFF_FW + (size_t)c * 1024;
        Ns = 1024; Kd = 2048;
    } else if (uid < A) {
        int j = uid - 10;
        src = aw + (size_t)j * DDC; dsto = OFF_AW + (size_t)j * M1; Ns = 1024; Kd = 1024;
    } else if (uid < Bu) {
        int tix = uid - A; int i = tix >> 2, c = tix & 3;
        src = w1 + (size_t)i * 4 * M1 + (size_t)c * 1024;
        dsto = OFF_W1 + (size_t)i * 4 * M1 + (size_t)c * M1;
        Ns = 4096; Kd = 1024;
    } else {
        int tix = uid - Bu; int i = tix >> 2, c = tix & 3;
        src = w2 + (size_t)i * 4 * M1 + (size_t)c * M1;
        dsto = OFF_W2 + (size_t)i * 4 * M1 + (size_t)c * 1024;
        Ns = 1024; Kd = 4096;
    }

    int n0 = blockIdx.x * 32, k0 = blockIdx.y * 32;
    int tx = threadIdx.x & 31, ty = threadIdx.x >> 5;
    for (int r = ty; r < 32; r += 8) t[r][tx] = src[(size_t)(k0 + r) * Ns + n0 + tx];
    __syncthreads();
    for (int r = ty; r < 32; r += 8)
        wt[dsto + (size_t)(n0 + r) * Kd + k0 + tx] = __float2half_rn(t[tx][r]);
}

__global__ void aconv_kernel(const float* __restrict__ x, half_t* o, int n)
{
    int i = (blockIdx.x * blockDim.x + threadIdx.x) * 4;
    if (i >= n) return;
    float4 v = *(const float4*)(x + i);
    *(__half2*)(o + i)     = __floats2half2_rn(v.x, v.y);
    *(__half2*)(o + i + 2) = __floats2half2_rn(v.z, v.w);
}

// ---------------------------------------------------------------------------
// Merged spatial+temporal attention.
// ---------------------------------------------------------------------------
#define SP68 68
#define SMEM_STA 34816

__global__ __launch_bounds__(256)
void st_attn(const half_t* __restrict__ q, const half_t* __restrict__ k,
             const half_t* __restrict__ v,
             const half_t* __restrict__ t1, const half_t* __restrict__ t2,
             const half_t* __restrict__ t3,
             const int* __restrict__ mask,
             half_t* __restrict__ osp, half_t* __restrict__ ote)
{
    extern __shared__ float S[];
    int tid = threadIdx.x;

    if (blockIdx.x < 2048) {
        int unit = tid >> 6, tu = tid & 63;
        int u = blockIdx.x * 4 + unit;
        int h = u & 15;
        int c = (u >> 4) & 63;
        int b = u >> 10;
        int tb = b * SEQ + c * 8;
        float* Qs = S + unit * 1696;
        float* Ks = Qs + 544;
        float* Vs = Ks + 544;
        float* Ps = Vs + 544;

        {
            int r = tu >> 3, d0 = (tu & 7) * 8;
            size_t g = (size_t)(tb + r) * DMODEL + h * DKH + d0;
            uint4 qv = *(const uint4*)(q + g);
            uint4 kv = *(const uint4*)(k + g);
            uint4 vv = *(const uint4*)(v + g);
            const __half2* qh = (const __half2*)&qv;
            const __half2* kh = (const __half2*)&kv;
            const __half2* vh = (const __half2*)&vv;
#pragma unroll
            for (int j = 0; j < 4; j++) {
                float2 f = __half22float2(qh[j]);
                Qs[r * SP68 + d0 + 2 * j] = f.x; Qs[r * SP68 + d0 + 2 * j + 1] = f.y;
                f = __half22float2(kh[j]);
                Ks[r * SP68 + d0 + 2 * j] = f.x; Ks[r * SP68 + d0 + 2 * j + 1] = f.y;
                f = __half22float2(vh[j]);
                Vs[r * SP68 + d0 + 2 * j] = f.x; Vs[r * SP68 + d0 + 2 * j + 1] = f.y;
            }
        }
        __syncthreads();

        int i = tu >> 3, j = tu & 7;
        float4 a4; a4.x = 0.f; a4.y = 0.f; a4.z = 0.f; a4.w = 0.f;
#pragma unroll
        for (int d = 0; d < 64; d += 4) {
            float4 qa = *(const float4*)&Qs[i * SP68 + d];
            float4 kb = *(const float4*)&Ks[j * SP68 + d];
            a4.x += qa.x * kb.x; a4.y += qa.y * kb.y;
            a4.z += qa.z * kb.z; a4.w += qa.w * kb.w;
        }
        float s = (a4.x + a4.y + a4.z + a4.w) * 0.125f;
        if (mask[b * SEQ + c * 8 + j] == 0) s = -1e9f;

        float m = s;
        m = fmaxf(m, __shfl_xor_sync(0xffffffffu, m, 1));
        m = fmaxf(m, __shfl_xor_sync(0xffffffffu, m, 2));
        m = fmaxf(m, __shfl_xor_sync(0xffffffffu, m, 4));
        float p = __expf(s - m);
        float sum = p;
        sum += __shfl_xor_sync(0xffffffffu, sum, 1);
        sum += __shfl_xor_sync(0xffffffffu, sum, 2);
        sum += __shfl_xor_sync(0xffffffffu, sum, 4);
        Ps[i * 8 + j] = p / sum;
        __syncthreads();

        {
            int r = tu >> 3, d0 = (tu & 7) * 8;
            float4 o0, o1;
            o0.x = o0.y = o0.z = o0.w = 0.f;
            o1.x = o1.y = o1.z = o1.w = 0.f;
#pragma unroll
            for (int jj = 0; jj < 8; jj++) {
                float pv = Ps[r * 8 + jj];
                float4 v0 = *(const float4*)&Vs[jj * SP68 + d0];
                float4 v1 = *(const float4*)&Vs[jj * SP68 + d0 + 4];
                o0.x += pv * v0.x; o0.y += pv * v0.y; o0.z += pv * v0.z; o0.w += pv * v0.w;
                o1.x += pv * v1.x; o1.y += pv * v1.y; o1.z += pv * v1.z; o1.w += pv * v1.w;
            }
            uint4 ov;
            ((uint32_t*)&ov)[0] = packh2(o0.x, o0.y);
            ((uint32_t*)&ov)[1] = packh2(o0.z, o0.w);
            ((uint32_t*)&ov)[2] = packh2(o1.x, o1.y);
            ((uint32_t*)&ov)[3] = packh2(o1.z, o1.w);
            *(uint4*)(osp + (size_t)(tb + r) * DMODEL + h * DKH + d0) = ov;
        }
    } else {
        int u = blockIdx.x - 2048;
        int h = u & 15;
        int jpos = (u >> 4) & 7;
        int b = u >> 7;
        int tx = tid & 15, ty = tid >> 4;
        half_t* QVh  = (half_t*)S;
        half_t* Ks2h = QVh + 64 * SP68;
        float*  Pst  = (float*)(Ks2h + 64 * SP68);

        for (int idx = tid; idx < 1024; idx += 256) {
            int r = idx >> 4;
            int d0 = (idx & 15) << 2;
            size_t g = (size_t)(b * SEQ + r * 8 + jpos) * DMODEL + h * DKH + d0;
            uint2 av = *(const uint2*)(t1 + g);
            const half_t* ah = (const half_t*)&av;
            QVh[(d0 + 0) * SP68 + r] = ah[0];
            QVh[(d0 + 1) * SP68 + r] = ah[1];
            QVh[(d0 + 2) * SP68 + r] = ah[2];
            QVh[(d0 + 3) * SP68 + r] = ah[3];
            uint2 kv = *(const uint2*)(t2 + g);
            const half_t* kh = (const half_t*)&kv;
            Ks2h[(d0 + 0) * SP68 + r] = kh[0];
            Ks2h[(d0 + 1) * SP68 + r] = kh[1];
            Ks2h[(d0 + 2) * SP68 + r] = kh[2];
            Ks2h[(d0 + 3) * SP68 + r] = kh[3];
        }
        __syncthreads();

        float acc[4][4];
#pragma unroll
        for (int i = 0; i < 4; i++)
#pragma unroll
            for (int j = 0; j < 4; j++) acc[i][j] = 0.f;

        for (int d = 0; d < 64; d++) {
            uint2 au = *(const uint2*)&QVh[d * SP68 + ty * 4];
            uint2 bu = *(const uint2*)&Ks2h[d * SP68 + tx * 4];
            const __half2* ah = (const __half2*)&au;
            const __half2* bh = (const __half2*)&bu;
            float2 a01 = __half22float2(ah[0]), a23 = __half22float2(ah[1]);
            float2 b01 = __half22float2(bh[0]), b23 = __half22float2(bh[1]);
            float av[4] = {a01.x, a01.y, a23.x, a23.y};
            float bv[4] = {b01.x, b01.y, b23.x, b23.y};
#pragma unroll
            for (int i = 0; i < 4; i++)
#pragma unroll
                for (int j = 0; j < 4; j++) acc[i][j] += av[i] * bv[j];
        }
#pragma unroll
        for (int jj = 0; jj < 4; jj++) {
            int cc = tx * 4 + jj;
            bool msk = (mask[b * SEQ + cc * 8 + jpos] == 0);
#pragma unroll
            for (int i = 0; i < 4; i++)
                Pst[cc * SP68 + ty * 4 + i] = msk ? -1e9f : acc[i][jj] * 0.125f;
        }
        __syncthreads();

        if (tid < 64) {
            float m = -1e30f;
            for (int cc = 0; cc < 64; cc++) m = fmaxf(m, Pst[cc * SP68 + tid]);
            float sum = 0.f;
            for (int cc = 0; cc < 64; cc++) {
                float p = __expf(Pst[cc * SP68 + tid] - m);
                Pst[cc * SP68 + tid] = p; sum += p;
            }
            float inv = 1.f / sum;
            for (int cc = 0; cc < 64; cc++) Pst[cc * SP68 + tid] *= inv;
        }
        __syncthreads();

        for (int idx = tid; idx < 1024; idx += 256) {
            int r = idx >> 4;
            int d0 = (idx & 15) << 2;
            size_t g = (size_t)(b * SEQ + r * 8 + jpos) * DMODEL + h * DKH + d0;
            *(uint2*)&QVh[r * SP68 + d0] = *(const uint2*)(t3 + g);
        }
        __syncthreads();

        float oacc[4][4];
#pragma unroll
        for (int i = 0; i < 4; i++)
#pragma unroll
            for (int j = 0; j < 4; j++) oacc[i][j] = 0.f;

        for (int kk = 0; kk < 64; kk++) {
            float4 av4 = *(const float4*)&Pst[kk * SP68 + ty * 4];
            uint2 bu = *(const uint2*)&QVh[kk * SP68 + tx * 4];
            const __half2* bh = (const __half2*)&bu;
            float2 b01 = __half22float2(bh[0]), b23 = __half22float2(bh[1]);
            float av[4] = {av4.x, av4.y, av4.z, av4.w};
            float bv[4] = {b01.x, b01.y, b23.x, b23.y};
#pragma unroll
            for (int i = 0; i < 4; i++)
#pragma unroll
                for (int j = 0; j < 4; j++) oacc[i][j] += av[i] * bv[j];
        }
#pragma unroll
        for (int i = 0; i < 4; i++) {
            uint2 ov;
            ((uint32_t*)&ov)[0] = packh2(oacc[i][0], oacc[i][1]);
            ((uint32_t*)&ov)[1] = packh2(oacc[i][2], oacc[i][3]);
            *(uint2*)(ote + (size_t)(b * SEQ + (ty * 4 + i) * 8 + jpos) * DMODEL +
                      h * DKH + tx * 4) = ov;
        }
    }
}

// ---------------------------------------------------------------------------
// LayerNorm: warp-per-row, 8 rows per 256-thread block.
// ---------------------------------------------------------------------------
__global__ __launch_bounds__(256)
void layernorm_kernel(const float* __restrict__ x,
                      const float* __restrict__ gamma,
                      const float* __restrict__ beta,
                      half_t* __restrict__ oh)
{
    int row = blockIdx.x * 8 + (threadIdx.x >> 5);
    int lane = threadIdx.x & 31;
    const float* xr = x + (size_t)row * DMODEL;

    float4 v[8];
    float s1 = 0.f, s2 = 0.f;
#pragma unroll
    for (int i = 0; i < 8; i++) {
        v[i] = *(const float4*)(xr + lane * 4 + i * 128);
        s1 += v[i].x + v[i].y + v[i].z + v[i].w;
        s2 += v[i].x * v[i].x + v[i].y * v[i].y + v[i].z * v[i].z + v[i].w * v[i].w;
    }
#pragma unroll
    for (int o = 16; o; o >>= 1) {
        s1 += __shfl_xor_sync(0xffffffffu, s1, o);
        s2 += __shfl_xor_sync(0xffffffffu, s2, o);
    }
    float mean = s1 * (1.f / DMODEL);
    float var = s2 * (1.f / DMODEL) - mean * mean;
    float inv = rsqrtf(var + LN_EPS);

#pragma unroll
    for (int i = 0; i < 8; i++) {
        int c = lane * 4 + i * 128;
        float4 g = *(const float4*)(gamma + c);
        float4 bb = *(const float4*)(beta + c);
        uint2 ov;
        ((uint32_t*)&ov)[0] = packh2((v[i].x - mean) * inv * g.x + bb.x,
                                     (v[i].y - mean) * inv * g.y + bb.y);
        ((uint32_t*)&ov)[1] = packh2((v[i].z - mean) * inv * g.z + bb.z,
                                     (v[i].w - mean) * inv * g.w + bb.w);
        *(uint2*)(oh + (size_t)row * DMODEL + c) = ov;
    }
}

// ---------------------------------------------------------------------------
// Host orchestration
// ---------------------------------------------------------------------------
extern "C" void kernel_launch(void* const* d_in, const int* in_sizes, int n_in,
                              void* d_out, int out_size)
{
    (void)n_in; (void)out_size;
    const float* x    = (const float*)d_in[0];
    const int*   mask = (const int*)  d_in[1];
    const float* sw   = (const float*)d_in[2];
    const float* sb   = (const float*)d_in[3];
    const float* tw   = (const float*)d_in[4];
    const float* tbia = (const float*)d_in[5];
    const float* fw   = (const float*)d_in[6];
    const float* fb   = (const float*)d_in[7];
    const float* aw   = (const float*)d_in[8];
    const float* ab   = (const float*)d_in[9];
    const float* w1   = (const float*)d_in[10];
    const float* b1   = (const float*)d_in[11];
    const float* w2   = (const float*)d_in[12];
    const float* b2   = (const float*)d_in[13];
    const float* lns  = (const float*)d_in[14];
    const float* lnb  = (const float*)d_in[15];
    float* out = (float*)d_out;

    cudaFuncSetAttribute(gemm_hmma<0>, cudaFuncAttributeMaxDynamicSharedMemorySize, SMEM_GEMM);
    cudaFuncSetAttribute(gemm_hmma<1>, cudaFuncAttributeMaxDynamicSharedMemorySize, SMEM_GEMM);
    cudaFuncSetAttribute(gemm_hmma<2>, cudaFuncAttributeMaxDynamicSharedMemorySize, SMEM_GEMM);
    cudaFuncSetAttribute(gemm_hmma<3>, cudaFuncAttributeMaxDynamicSharedMemorySize, SMEM_GEMM);
    cudaFuncSetAttribute(flash_attn,   cudaFuncAttributeMaxDynamicSharedMemorySize, SMEM_FLASH);
    cudaFuncSetAttribute(st_attn,      cudaFuncAttributeMaxDynamicSharedMemorySize, SMEM_STA);

    half_t *wt, *xh, *hh, *ah, *fh, *qkvh, *q, *k, *v, *t1, *t2, *t3;
    float *xb;
    cudaGetSymbolAddress((void**)&wt,   g_wt);
    cudaGetSymbolAddress((void**)&xh,   g_xh);
    cudaGetSymbolAddress((void**)&hh,   g_hh);
    cudaGetSymbolAddress((void**)&ah,   g_ah);
    cudaGetSymbolAddress((void**)&fh,   g_fh);
    cudaGetSymbolAddress((void**)&qkvh, g_qkvh);
    cudaGetSymbolAddress((void**)&q,    g_q);
    cudaGetSymbolAddress((void**)&k,    g_k);
    cudaGetSymbolAddress((void**)&v,    g_v);
    cudaGetSymbolAddress((void**)&t1,   g_t1);
    cudaGetSymbolAddress((void**)&t2,   g_t2);
    cudaGetSymbolAddress((void**)&t3,   g_t3);
    cudaGetSymbolAddress((void**)&xb,   g_xb);

    const size_t DD = (size_t)DMODEL * DMODEL;
    int nlayers = in_sizes[8] / (int)(4 * DD);

    wconv_all<<<dim3(32, 32, 10 + 12 * nlayers), 256>>>(sw, tw, fw, aw, w1, w2, wt, nlayers);
    aconv_kernel<<<(MTOK * DMODEL / 4 + 255) / 256, 256>>>(x, xh, MTOK * DMODEL);

    gemm_hmma<2><<<dim3(48, 32), 256, SMEM_GEMM>>>(
        xh, wt + OFF_ST, nullptr, nullptr, sb, tbia, nullptr, nullptr, nullptr,
        MTOK, 6144, DMODEL, 0, 0, q, k, v, t1, t2, t3);

    st_attn<<<3072, 256, SMEM_STA>>>(q, k, v, t1, t2, t3, mask, ah, hh);

    gemm_hmma<3><<<dim3(8, 32, 2), 256, SMEM_GEMM>>>(
        ah, wt + OFF_SW3, hh, wt + OFF_TW3, sb + 3 * DMODEL, tbia + 3 * DMODEL,
        nullptr, nullptr, fh, MTOK, DMODEL, DMODEL, 0, 2048,
        nullptr, nullptr, nullptr, nullptr, nullptr, nullptr);

    gemm_hmma<0><<<dim3(8, 32), 256, SMEM_GEMM>>>(
        fh, wt + OFF_FW, nullptr, nullptr, fb, nullptr, nullptr, xb, nullptr,
        MTOK, DMODEL, 2 * DMODEL, 0, DMODEL, nullptr, nullptr, nullptr, nullptr, nullptr, nullptr);

    for (int i = 0; i < nlayers; i++) {
        const float* abi = ab + (size_t)i * 4 * DMODEL;
        const half_t* awi = wt + OFF_AW + (size_t)i * 4 * M1;

        layernorm_kernel<<<MTOK / 8, 256>>>(xb, lns + (i * 2 + 0) * DMODEL,
                                            lnb + (i * 2 + 0) * DMODEL, hh);
        gemm_hmma<1><<<dim3(24, 32), 256, SMEM_GEMM>>>(
            hh, awi, nullptr, nullptr, abi, nullptr, nullptr, nullptr, qkvh,
            MTOK, 3 * DMODEL, DMODEL, 0, 0, nullptr, nullptr, nullptr, nullptr, nullptr, nullptr);

        flash_attn<<<dim3(4, 128), 256, SMEM_FLASH>>>(qkvh, mask, ah);

        gemm_hmma<0><<<dim3(8, 32), 256, SMEM_GEMM>>>(
            ah, awi + 3 * M1, nullptr, nullptr, abi + 3 * DMODEL, nullptr, xb, xb, nullptr,
            MTOK, DMODEL, DMODEL, 0, DMODEL, nullptr, nullptr, nullptr, nullptr, nullptr, nullptr);

        layernorm_kernel<<<MTOK / 8, 256>>>(xb, lns + (i * 2 + 1) * DMODEL,
                                            lnb + (i * 2 + 1) * DMODEL, hh);
        gemm_hmma<0><<<dim3(32, 32), 256, SMEM_GEMM>>>(
            hh, wt + OFF_W1 + (size_t)i * 4 * M1, nullptr, nullptr, b1 + i * DFF, nullptr,
            nullptr, nullptr, fh, MTOK, DFF, DMODEL, 1, DFF,
            nullptr, nullptr, nullptr, nullptr, nullptr, nullptr);
        float* dst = (i == nlayers - 1) ? out : xb;
        gemm_hmma<0><<<dim3(8, 32), 256, SMEM_GEMM>>>(
            fh, wt + OFF_W2 + (size_t)i * 4 * M1, nullptr, nullptr, b2 + i * DMODEL, nullptr,
            xb, dst, nullptr, MTOK, DMODEL, DFF, 0, DMODEL,
            nullptr, nullptr, nullptr, nullptr, nullptr, nullptr);
    }
}

// round 11
// speedup vs baseline: 1.0682x; 1.0242x over previous
#include <cuda_runtime.h>
#include <cuda_fp16.h>
#include <cstdint>
#include <math.h>

#define DMODEL 1024
#define BATCH  8
#define SEQ    512
#define NHEAD  16
#define DKH    64
#define MTOK   4096
#define DFF    4096
#define NCLIP  64
#define LN_EPS 1e-5f

typedef __half half_t;

// ---------------------------------------------------------------------------
// PTX helpers (arch-agnostic: mma.sync / ldmatrix / cp.async / griddepcontrol)
// ---------------------------------------------------------------------------
__device__ __forceinline__ uint32_t smem_u32(const void* p) {
    uint32_t a;
    asm("{ .reg .u64 t; cvta.to.shared.u64 t, %1; cvt.u32.u64 %0, t; }" : "=r"(a) : "l"(p));
    return a;
}

#define LDSM4(r, a) \
    asm volatile("ldmatrix.sync.aligned.m8n8.x4.shared.b16 {%0,%1,%2,%3}, [%4];" \
        : "=r"((r)[0]), "=r"((r)[1]), "=r"((r)[2]), "=r"((r)[3]) : "r"(a))

#define LDSM4T(r, a) \
    asm volatile("ldmatrix.sync.aligned.m8n8.x4.trans.shared.b16 {%0,%1,%2,%3}, [%4];" \
        : "=r"((r)[0]), "=r"((r)[1]), "=r"((r)[2]), "=r"((r)[3]) : "r"(a))

#define MMA16816(c, a, b0, b1) \
    asm volatile("mma.sync.aligned.m16n8k16.row.col.f32.f16.f16.f32 " \
        "{%0,%1,%2,%3}, {%4,%5,%6,%7}, {%8,%9}, {%0,%1,%2,%3};" \
        : "+f"((c)[0]), "+f"((c)[1]), "+f"((c)[2]), "+f"((c)[3]) \
        : "r"((a)[0]), "r"((a)[1]), "r"((a)[2]), "r"((a)[3]), "r"(b0), "r"(b1))

#define CPASYNC16(d, s) asm volatile("cp.async.cg.shared.global [%0], [%1], 16;" :: "r"(d), "l"(s))
#define CPCOMMIT()      asm volatile("cp.async.commit_group;" ::: "memory")
#define CPWAIT(n)       asm volatile("cp.async.wait_group %0;" :: "n"(n) : "memory")

#define PDL_WAIT()    asm volatile("griddepcontrol.wait;" ::: "memory")
#define PDL_TRIGGER() asm volatile("griddepcontrol.launch_dependents;" ::: "memory")

__device__ __forceinline__ uint32_t packh2(float x, float y) {
    __half2 h = __floats2half2_rn(x, y);
    return *(uint32_t*)&h;
}

// ---------------------------------------------------------------------------
// Device scratch
// ---------------------------------------------------------------------------
#define WT_TOT (34u * 1024u * 1024u)
__device__ half_t g_wt[WT_TOT];
__device__ half_t g_xh[MTOK * DMODEL];
__device__ half_t g_hh[MTOK * DMODEL];
__device__ half_t g_ah[MTOK * DMODEL];
__device__ half_t g_fh[MTOK * DFF];
__device__ half_t g_qkvh[3 * 128 * SEQ * DKH];
__device__ half_t g_q[MTOK * DMODEL];
__device__ half_t g_k[MTOK * DMODEL];
__device__ half_t g_v[MTOK * DMODEL];
__device__ half_t g_t1[MTOK * DMODEL];
__device__ half_t g_t2[MTOK * DMODEL];
__device__ half_t g_t3[MTOK * DMODEL];
__device__ float  g_xb[MTOK * DMODEL];

// weight offsets (units of 1M elements) inside g_wt
#define M1 (1024u * 1024u)
#define DDC (1024u * 1024u)
#define OFF_ST  0u
#define OFF_SW3 (6u * M1)
#define OFF_TW3 (7u * M1)
#define OFF_FW  (8u * M1)
#define OFF_AW  (10u * M1)
#define OFF_W1  (18u * M1)
#define OFF_W2  (26u * M1)

// ---------------------------------------------------------------------------
// fp16 HMMA GEMM, BK=64, 3-stage cp.async, 2 CTAs/SM, PDL-enabled:
// B (weights, old data) prefetched BEFORE griddepcontrol.wait; A after.
// Trigger after main loop so the successor overlaps our epilogue.
// MODE 0: standard; MODE 1: QKV scatter; MODE 2: six fp16 buffers;
// MODE 3: z-batched out-proj.
// ---------------------------------------------------------------------------
#define STAGES 3
#define STAGE_BYTES 32768
#define SMEM_GEMM (STAGES * STAGE_BYTES)

template<int MODE>
__global__ __launch_bounds__(256, 2)
void gemm_hmma(const half_t* __restrict__ A, const half_t* __restrict__ B,
               const half_t* __restrict__ A2, const half_t* __restrict__ B2,
               const float* __restrict__ bias, const float* __restrict__ bias2,
               const float* __restrict__ R, float* Cf, half_t* Ch,
               int M, int N, int K, int relu, int ldC,
               half_t* q0, half_t* q1, half_t* q2, half_t* q3, half_t* q4, half_t* q5)
{
    extern __shared__ char smem[];
    uint32_t sb = smem_u32(smem);
    const int tid = threadIdx.x;
    const int lane = tid & 31, warp = tid >> 5;
    const int row0 = blockIdx.y * 128, col0 = blockIdx.x * 128;
    const int wm = (warp >> 2) * 64;
    const int wn = (warp & 3) * 32;

    if (MODE == 3 && blockIdx.z == 1) { A = A2; B = B2; bias = bias2; }

    int segr[4], segc[4];
#pragma unroll
    for (int i = 0; i < 4; i++) { int s = tid + i * 256; segr[i] = s >> 3; segc[i] = s & 7; }

    int rA[4], swA[4];
#pragma unroll
    for (int mt = 0; mt < 4; mt++) {
        int r = wm + mt * 16 + (lane & 15);
        rA[mt] = r; swA[mt] = r & 7;
    }
    int rB[2], swB[2];
#pragma unroll
    for (int n2 = 0; n2 < 2; n2++) {
        int r = wn + n2 * 16 + (lane & 7) + ((lane >> 4) << 3);
        rB[n2] = r; swB[n2] = r & 7;
    }
    const int csA = lane >> 4;
    const int csB = (lane >> 3) & 1;

    float acc[4][4][4];
#pragma unroll
    for (int mt = 0; mt < 4; mt++)
#pragma unroll
        for (int nt = 0; nt < 4; nt++)
#pragma unroll
            for (int i = 0; i < 4; i++) acc[mt][nt][i] = 0.f;

    const int NT = K >> 6;

#define GISSUE_B(kt, st) do { \
    uint32_t sB_ = sb + (st) * STAGE_BYTES + 16384; \
    _Pragma("unroll") for (int i = 0; i < 4; i++) { \
        int r_ = segr[i], c_ = segc[i]; \
        uint32_t sw_ = (uint32_t)((c_ ^ (r_ & 7)) << 4); \
        CPASYNC16(sB_ + r_ * 128 + sw_, B + (size_t)(col0 + r_) * K + (size_t)(kt) * 64 + c_ * 8); \
    } \
    CPCOMMIT(); } while (0)

#define GISSUE_A(kt, st) do { \
    uint32_t sA_ = sb + (st) * STAGE_BYTES; \
    _Pragma("unroll") for (int i = 0; i < 4; i++) { \
        int r_ = segr[i], c_ = segc[i]; \
        uint32_t sw_ = (uint32_t)((c_ ^ (r_ & 7)) << 4); \
        CPASYNC16(sA_ + r_ * 128 + sw_, A + (size_t)(row0 + r_) * K + (size_t)(kt) * 64 + c_ * 8); \
    } \
    CPCOMMIT(); } while (0)

#define GISSUE(kt, st) do { \
    uint32_t sA_ = sb + (st) * STAGE_BYTES; \
    uint32_t sB_ = sA_ + 16384; \
    _Pragma("unroll") for (int i = 0; i < 4; i++) { \
        int r_ = segr[i], c_ = segc[i]; \
        uint32_t sw_ = (uint32_t)((c_ ^ (r_ & 7)) << 4); \
        CPASYNC16(sA_ + r_ * 128 + sw_, A + (size_t)(row0 + r_) * K + (size_t)(kt) * 64 + c_ * 8); \
        CPASYNC16(sB_ + r_ * 128 + sw_, B + (size_t)(col0 + r_) * K + (size_t)(kt) * 64 + c_ * 8); \
    } \
    CPCOMMIT(); } while (0)

    // Weights are old data (written by wconv_all, sealed before any PDL
    // early-start window) -> prefetch before the dependency wait.
    GISSUE_B(0, 0);          // group 0
    GISSUE_B(1, 1);          // group 1
    PDL_WAIT();
    GISSUE_A(0, 0);          // group 2
    GISSUE_A(1, 1);          // group 3

    for (int kt = 0; kt < NT; kt++) {
        // groups complete in order: wait_group(1) guarantees B(kt)&A(kt) ready
        if (kt == NT - 1) { CPWAIT(0); } else { CPWAIT(1); }
        __syncthreads();
        if (kt + 2 < NT) GISSUE(kt + 2, (kt + 2) % 3);

        uint32_t sA = sb + (kt % 3) * STAGE_BYTES;
        uint32_t sB = sA + 16384;
#pragma unroll
        for (int k16 = 0; k16 < 4; k16++) {
            uint32_t ra[4][4], rb[2][4];
#pragma unroll
            for (int mt = 0; mt < 4; mt++)
                LDSM4(ra[mt], sA + rA[mt] * 128 + ((((k16 << 1) + csA) ^ swA[mt]) << 4));
#pragma unroll
            for (int n2 = 0; n2 < 2; n2++)
                LDSM4(rb[n2], sB + rB[n2] * 128 + ((((k16 << 1) + csB) ^ swB[n2]) << 4));
#pragma unroll
            for (int mt = 0; mt < 4; mt++)
#pragma unroll
                for (int nt = 0; nt < 4; nt++)
                    MMA16816(acc[mt][nt], ra[mt],
                             rb[nt >> 1][(nt & 1) * 2], rb[nt >> 1][(nt & 1) * 2 + 1]);
        }
    }

    PDL_TRIGGER();   // successor may launch & prefetch while we run epilogue

    // Epilogue
    half_t* obuf = nullptr;
    if (MODE == 2) {
        int bsel = col0 >> 10;
        obuf = (bsel == 0) ? q0 : (bsel == 1) ? q1 : (bsel == 2) ? q2 :
               (bsel == 3) ? q3 : (bsel == 4) ? q4 : q5;
    }
    const int cbase = (MODE == 3) ? (int)blockIdx.z * 1024 : 0;
#pragma unroll
    for (int mt = 0; mt < 4; mt++) {
        int rg = row0 + wm + mt * 16 + (lane >> 2);
#pragma unroll
        for (int nt = 0; nt < 4; nt++) {
            int c = col0 + wn + nt * 8 + (lane & 3) * 2;
            float* a = acc[mt][nt];
#pragma unroll
            for (int h = 0; h < 2; h++) {
                int row = rg + h * 8;
                float v0 = a[h * 2], v1 = a[h * 2 + 1];
                if (MODE == 0) {
                    if (bias) { v0 += bias[c]; v1 += bias[c + 1]; }
                    if (R) {
                        float2 rr = *(const float2*)(R + (size_t)row * N + c);
                        v0 += rr.x; v1 += rr.y;
                    }
                    if (relu) { v0 = fmaxf(v0, 0.f); v1 = fmaxf(v1, 0.f); }
                    if (Cf) {
                        float2 o; o.x = v0; o.y = v1;
                        *(float2*)(Cf + (size_t)row * ldC + c) = o;
                    }
                    if (Ch)
                        *(__half2*)(Ch + (size_t)row * ldC + c) = __floats2half2_rn(v0, v1);
                } else if (MODE == 1) {
                    v0 += bias[c]; v1 += bias[c + 1];
                    int qkv = c >> 10, hh_ = (c >> 6) & 15, d = c & 63;
                    int b = row >> 9, srow = row & 511;
                    size_t dst = (((size_t)(qkv * 128 + b * 16 + hh_) * 512) + srow) * 64 + d;
                    *(__half2*)(Ch + dst) = __floats2half2_rn(v0, v1);
                } else if (MODE == 2) {
                    float b0v = (c < 3072) ? bias[c] : bias2[c - 3072];
                    float b1v = (c + 1 < 3072) ? bias[c + 1] : bias2[c + 1 - 3072];
                    *(__half2*)(obuf + (size_t)row * 1024 + (c & 1023)) =
                        __floats2half2_rn(v0 + b0v, v1 + b1v);
                } else { // MODE 3
                    v0 += bias[c]; v1 += bias[c + 1];
                    *(__half2*)(Ch + (size_t)row * ldC + cbase + c) = __floats2half2_rn(v0, v1);
                }
            }
        }
    }
}

// ---------------------------------------------------------------------------
// Flash attention (encoder): per (b,h) 512x512, fp16 mma, online softmax.
// ---------------------------------------------------------------------------
#define FLD 72
#define SMEM_FLASH (3 * 128 * FLD * 2 + 512)

__global__ __launch_bounds__(256)
void flash_attn(const half_t* __restrict__ qkvh, const int* __restrict__ mask,
                half_t* __restrict__ out)
{
    extern __shared__ char sm[];
    half_t* Qs = (half_t*)sm;
    half_t* Ks = Qs + 128 * FLD;
    half_t* Vs = Ks + 128 * FLD;
    float*  mf = (float*)(Vs + 128 * FLD);

    const int bh = blockIdx.y, qt = blockIdx.x;
    const int b = bh >> 4, hd = bh & 15;
    const int tid = threadIdx.x, lane = tid & 31, warp = tid >> 5;
    const int m0 = warp * 16;

    PDL_WAIT();

    const half_t* Qg = qkvh + (((size_t)(0 * 128 + bh) * 512) + qt * 128) * 64;
    const half_t* Kg = qkvh + ((size_t)(1 * 128 + bh) * 512) * 64;
    const half_t* Vg = qkvh + ((size_t)(2 * 128 + bh) * 512) * 64;

    for (int i = tid; i < 1024; i += 256) {
        int r = i >> 3, cs = i & 7;
        *(uint4*)(Qs + r * FLD + cs * 8) = *(const uint4*)(Qg + r * 64 + cs * 8);
    }
    __syncthreads();

    uint32_t qf[4][4];
#pragma unroll
    for (int kb = 0; kb < 4; kb++)
        LDSM4(qf[kb], smem_u32(Qs + (m0 + (lane & 15)) * FLD + kb * 16 + (lane >> 4) * 8));

    float mrow[2] = {-1e30f, -1e30f};
    float lrow[2] = {0.f, 0.f};
    float oacc[8][4];
#pragma unroll
    for (int i = 0; i < 8; i++)
#pragma unroll
        for (int j = 0; j < 4; j++) oacc[i][j] = 0.f;

    for (int kt = 0; kt < 4; kt++) {
        __syncthreads();
        for (int i = tid; i < 1024; i += 256) {
            int r = i >> 3, cs = i & 7;
            *(uint4*)(Ks + r * FLD + cs * 8) = *(const uint4*)(Kg + (kt * 128 + r) * 64 + cs * 8);
            *(uint4*)(Vs + r * FLD + cs * 8) = *(const uint4*)(Vg + (kt * 128 + r) * 64 + cs * 8);
        }
        if (tid < 128) mf[tid] = (mask[b * SEQ + kt * 128 + tid] == 0) ? 1.f : 0.f;
        __syncthreads();

        float s[16][4];
#pragma unroll
        for (int f = 0; f < 16; f++)
#pragma unroll
            for (int i = 0; i < 4; i++) s[f][i] = 0.f;

#pragma unroll
        for (int kb = 0; kb < 4; kb++) {
#pragma unroll
            for (int nb2 = 0; nb2 < 8; nb2++) {
                uint32_t bf[4];
                int krow = nb2 * 16 + (lane & 7) + ((lane >> 4) & 1) * 8;
                int kcol = kb * 16 + ((lane >> 3) & 1) * 8;
                LDSM4(bf, smem_u32(Ks + krow * FLD + kcol));
                MMA16816(s[2 * nb2],     qf[kb], bf[0], bf[1]);
                MMA16816(s[2 * nb2 + 1], qf[kb], bf[2], bf[3]);
            }
        }

#pragma unroll
        for (int f = 0; f < 16; f++) {
            int c0 = f * 8 + (lane & 3) * 2;
            float f0 = mf[c0], f1 = mf[c0 + 1];
            s[f][0] = (f0 != 0.f) ? -1e9f : s[f][0] * 0.125f;
            s[f][1] = (f1 != 0.f) ? -1e9f : s[f][1] * 0.125f;
            s[f][2] = (f0 != 0.f) ? -1e9f : s[f][2] * 0.125f;
            s[f][3] = (f1 != 0.f) ? -1e9f : s[f][3] * 0.125f;
        }

        float mx0 = -1e30f, mx1 = -1e30f;
#pragma unroll
        for (int f = 0; f < 16; f++) {
            mx0 = fmaxf(mx0, fmaxf(s[f][0], s[f][1]));
            mx1 = fmaxf(mx1, fmaxf(s[f][2], s[f][3]));
        }
        mx0 = fmaxf(mx0, __shfl_xor_sync(0xffffffffu, mx0, 1));
        mx0 = fmaxf(mx0, __shfl_xor_sync(0xffffffffu, mx0, 2));
        mx1 = fmaxf(mx1, __shfl_xor_sync(0xffffffffu, mx1, 1));
        mx1 = fmaxf(mx1, __shfl_xor_sync(0xffffffffu, mx1, 2));

        float Mn0 = fmaxf(mrow[0], mx0), Mn1 = fmaxf(mrow[1], mx1);
        float sc0 = __expf(mrow[0] - Mn0), sc1 = __expf(mrow[1] - Mn1);
        mrow[0] = Mn0; mrow[1] = Mn1;

        float rs0 = 0.f, rs1 = 0.f;
#pragma unroll
        for (int f = 0; f < 16; f++) {
            s[f][0] = __expf(s[f][0] - Mn0); s[f][1] = __expf(s[f][1] - Mn0);
            s[f][2] = __expf(s[f][2] - Mn1); s[f][3] = __expf(s[f][3] - Mn1);
            rs0 += s[f][0] + s[f][1];
            rs1 += s[f][2] + s[f][3];
        }
        rs0 += __shfl_xor_sync(0xffffffffu, rs0, 1);
        rs0 += __shfl_xor_sync(0xffffffffu, rs0, 2);
        rs1 += __shfl_xor_sync(0xffffffffu, rs1, 1);
        rs1 += __shfl_xor_sync(0xffffffffu, rs1, 2);
        lrow[0] = lrow[0] * sc0 + rs0;
        lrow[1] = lrow[1] * sc1 + rs1;

#pragma unroll
        for (int nb = 0; nb < 8; nb++) {
            oacc[nb][0] *= sc0; oacc[nb][1] *= sc0;
            oacc[nb][2] *= sc1; oacc[nb][3] *= sc1;
        }

#pragma unroll
        for (int kb = 0; kb < 8; kb++) {
            uint32_t a[4];
            a[0] = packh2(s[2 * kb][0],     s[2 * kb][1]);
            a[1] = packh2(s[2 * kb][2],     s[2 * kb][3]);
            a[2] = packh2(s[2 * kb + 1][0], s[2 * kb + 1][1]);
            a[3] = packh2(s[2 * kb + 1][2], s[2 * kb + 1][3]);
#pragma unroll
            for (int nb2 = 0; nb2 < 4; nb2++) {
                uint32_t vf[4];
                int srow = kb * 16 + (lane & 15);
                int dcol = nb2 * 16 + (lane >> 4) * 8;
                LDSM4T(vf, smem_u32(Vs + srow * FLD + dcol));
                MMA16816(oacc[2 * nb2],     a, vf[0], vf[1]);
                MMA16816(oacc[2 * nb2 + 1], a, vf[2], vf[3]);
            }
        }
    }

    PDL_TRIGGER();

    float inv0 = 1.f / lrow[0], inv1 = 1.f / lrow[1];
    int r0 = qt * 128 + m0 + (lane >> 2);
#pragma unroll
    for (int nb = 0; nb < 8; nb++) {
        int c = hd * 64 + nb * 8 + (lane & 3) * 2;
        *(__half2*)(out + (size_t)(b * SEQ + r0) * DMODEL + c) =
            __floats2half2_rn(oacc[nb][0] * inv0, oacc[nb][1] * inv0);
        *(__half2*)(out + (size_t)(b * SEQ + r0 + 8) * DMODEL + c) =
            __floats2half2_rn(oacc[nb][2] * inv1, oacc[nb][3] * inv1);
    }
}

// ---------------------------------------------------------------------------
// ALL weight conversions in one launch.
// ---------------------------------------------------------------------------
__global__ void wconv_all(const float* __restrict__ sw, const float* __restrict__ tw,
                          const float* __restrict__ fw, const float* __restrict__ aw,
                          const float* __restrict__ w1, const float* __restrict__ w2,
                          half_t* __restrict__ wt, int nlayers)
{
    __shared__ float t[32][33];
    int uid = blockIdx.z;
    const float* src;
    size_t dsto;
    int Ns, Kd;
    int A = 10 + 4 * nlayers;
    int Bu = A + 4 * nlayers;

    if (uid < 6) {
        src = (uid < 3) ? (sw + (size_t)uid * DDC) : (tw + (size_t)(uid - 3) * DDC);
        dsto = OFF_ST + (size_t)uid * M1; Ns = 1024; Kd = 1024;
    } else if (uid == 6) {
        src = sw + 3 * (size_t)DDC; dsto = OFF_SW3; Ns = 1024; Kd = 1024;
    } else if (uid == 7) {
        src = tw + 3 * (size_t)DDC; dsto = OFF_TW3; Ns = 1024; Kd = 1024;
    } else if (uid < 10) {
        int c = uid - 8;
        src = fw + (size_t)c * 1024 * 1024; dsto = OFF_FW + (size_t)c * 1024;
        Ns = 1024; Kd = 2048;
    } else if (uid < A) {
        int j = uid - 10;
        src = aw + (size_t)j * DDC; dsto = OFF_AW + (size_t)j * M1; Ns = 1024; Kd = 1024;
    } else if (uid < Bu) {
        int tix = uid - A; int i = tix >> 2, c = tix & 3;
        src = w1 + (size_t)i * 4 * M1 + (size_t)c * 1024;
        dsto = OFF_W1 + (size_t)i * 4 * M1 + (size_t)c * M1;
        Ns = 4096; Kd = 1024;
    } else {
        int tix = uid - Bu; int i = tix >> 2, c = tix & 3;
        src = w2 + (size_t)i * 4 * M1 + (size_t)c * M1;
        dsto = OFF_W2 + (size_t)i * 4 * M1 + (size_t)c * 1024;
        Ns = 1024; Kd = 4096;
    }

    int n0 = blockIdx.x * 32, k0 = blockIdx.y * 32;
    int tx = threadIdx.x & 31, ty = threadIdx.x >> 5;
    for (int r = ty; r < 32; r += 8) t[r][tx] = src[(size_t)(k0 + r) * Ns + n0 + tx];
    __syncthreads();
    for (int r = ty; r < 32; r += 8)
        wt[dsto + (size_t)(n0 + r) * Kd + k0 + tx] = __float2half_rn(t[tx][r]);
}

__global__ void aconv_kernel(const float* __restrict__ x, half_t* o, int n)
{
    int i = (blockIdx.x * blockDim.x + threadIdx.x) * 4;
    if (i >= n) return;
    float4 v = *(const float4*)(x + i);
    *(__half2*)(o + i)     = __floats2half2_rn(v.x, v.y);
    *(__half2*)(o + i + 2) = __floats2half2_rn(v.z, v.w);
}

// ---------------------------------------------------------------------------
// Merged spatial+temporal attention.
// ---------------------------------------------------------------------------
#define SP68 68
#define SMEM_STA 34816

__global__ __launch_bounds__(256)
void st_attn(const half_t* __restrict__ q, const half_t* __restrict__ k,
             const half_t* __restrict__ v,
             const half_t* __restrict__ t1, const half_t* __restrict__ t2,
             const half_t* __restrict__ t3,
             const int* __restrict__ mask,
             half_t* __restrict__ osp, half_t* __restrict__ ote)
{
    extern __shared__ float S[];
    int tid = threadIdx.x;

    PDL_WAIT();

    if (blockIdx.x < 2048) {
        int unit = tid >> 6, tu = tid & 63;
        int u = blockIdx.x * 4 + unit;
        int h = u & 15;
        int c = (u >> 4) & 63;
        int b = u >> 10;
        int tb = b * SEQ + c * 8;
        float* Qs = S + unit * 1696;
        float* Ks = Qs + 544;
        float* Vs = Ks + 544;
        float* Ps = Vs + 544;

        {
            int r = tu >> 3, d0 = (tu & 7) * 8;
            size_t g = (size_t)(tb + r) * DMODEL + h * DKH + d0;
            uint4 qv = *(const uint4*)(q + g);
            uint4 kv = *(const uint4*)(k + g);
            uint4 vv = *(const uint4*)(v + g);
            const __half2* qh = (const __half2*)&qv;
            const __half2* kh = (const __half2*)&kv;
            const __half2* vh = (const __half2*)&vv;
#pragma unroll
            for (int j = 0; j < 4; j++) {
                float2 f = __half22float2(qh[j]);
                Qs[r * SP68 + d0 + 2 * j] = f.x; Qs[r * SP68 + d0 + 2 * j + 1] = f.y;
                f = __half22float2(kh[j]);
                Ks[r * SP68 + d0 + 2 * j] = f.x; Ks[r * SP68 + d0 + 2 * j + 1] = f.y;
                f = __half22float2(vh[j]);
                Vs[r * SP68 + d0 + 2 * j] = f.x; Vs[r * SP68 + d0 + 2 * j + 1] = f.y;
            }
        }
        __syncthreads();

        int i = tu >> 3, j = tu & 7;
        float4 a4; a4.x = 0.f; a4.y = 0.f; a4.z = 0.f; a4.w = 0.f;
#pragma unroll
        for (int d = 0; d < 64; d += 4) {
            float4 qa = *(const float4*)&Qs[i * SP68 + d];
            float4 kb = *(const float4*)&Ks[j * SP68 + d];
            a4.x += qa.x * kb.x; a4.y += qa.y * kb.y;
            a4.z += qa.z * kb.z; a4.w += qa.w * kb.w;
        }
        float s = (a4.x + a4.y + a4.z + a4.w) * 0.125f;
        if (mask[b * SEQ + c * 8 + j] == 0) s = -1e9f;

        float m = s;
        m = fmaxf(m, __shfl_xor_sync(0xffffffffu, m, 1));
        m = fmaxf(m, __shfl_xor_sync(0xffffffffu, m, 2));
        m = fmaxf(m, __shfl_xor_sync(0xffffffffu, m, 4));
        float p = __expf(s - m);
        float sum = p;
        sum += __shfl_xor_sync(0xffffffffu, sum, 1);
        sum += __shfl_xor_sync(0xffffffffu, sum, 2);
        sum += __shfl_xor_sync(0xffffffffu, sum, 4);
        Ps[i * 8 + j] = p / sum;
        __syncthreads();

        PDL_TRIGGER();

        {
            int r = tu >> 3, d0 = (tu & 7) * 8;
            float4 o0, o1;
            o0.x = o0.y = o0.z = o0.w = 0.f;
            o1.x = o1.y = o1.z = o1.w = 0.f;
#pragma unroll
            for (int jj = 0; jj < 8; jj++) {
                float pv = Ps[r * 8 + jj];
                float4 v0 = *(const float4*)&Vs[jj * SP68 + d0];
                float4 v1 = *(const float4*)&Vs[jj * SP68 + d0 + 4];
                o0.x += pv * v0.x; o0.y += pv * v0.y; o0.z += pv * v0.z; o0.w += pv * v0.w;
                o1.x += pv * v1.x; o1.y += pv * v1.y; o1.z += pv * v1.z; o1.w += pv * v1.w;
            }
            uint4 ov;
            ((uint32_t*)&ov)[0] = packh2(o0.x, o0.y);
            ((uint32_t*)&ov)[1] = packh2(o0.z, o0.w);
            ((uint32_t*)&ov)[2] = packh2(o1.x, o1.y);
            ((uint32_t*)&ov)[3] = packh2(o1.z, o1.w);
            *(uint4*)(osp + (size_t)(tb + r) * DMODEL + h * DKH + d0) = ov;
        }
    } else {
        int u = blockIdx.x - 2048;
        int h = u & 15;
        int jpos = (u >> 4) & 7;
        int b = u >> 7;
        int tx = tid & 15, ty = tid >> 4;
        half_t* QVh  = (half_t*)S;
        half_t* Ks2h = QVh + 64 * SP68;
        float*  Pst  = (float*)(Ks2h + 64 * SP68);

        for (int idx = tid; idx < 1024; idx += 256) {
            int r = idx >> 4;
            int d0 = (idx & 15) << 2;
            size_t g = (size_t)(b * SEQ + r * 8 + jpos) * DMODEL + h * DKH + d0;
            uint2 av = *(const uint2*)(t1 + g);
            const half_t* ah = (const half_t*)&av;
            QVh[(d0 + 0) * SP68 + r] = ah[0];
            QVh[(d0 + 1) * SP68 + r] = ah[1];
            QVh[(d0 + 2) * SP68 + r] = ah[2];
            QVh[(d0 + 3) * SP68 + r] = ah[3];
            uint2 kv = *(const uint2*)(t2 + g);
            const half_t* kh = (const half_t*)&kv;
            Ks2h[(d0 + 0) * SP68 + r] = kh[0];
            Ks2h[(d0 + 1) * SP68 + r] = kh[1];
            Ks2h[(d0 + 2) * SP68 + r] = kh[2];
            Ks2h[(d0 + 3) * SP68 + r] = kh[3];
        }
        __syncthreads();

        float acc[4][4];
#pragma unroll
        for (int i = 0; i < 4; i++)
#pragma unroll
            for (int j = 0; j < 4; j++) acc[i][j] = 0.f;

        for (int d = 0; d < 64; d++) {
            uint2 au = *(const uint2*)&QVh[d * SP68 + ty * 4];
            uint2 bu = *(const uint2*)&Ks2h[d * SP68 + tx * 4];
            const __half2* ah = (const __half2*)&au;
            const __half2* bh = (const __half2*)&bu;
            float2 a01 = __half22float2(ah[0]), a23 = __half22float2(ah[1]);
            float2 b01 = __half22float2(bh[0]), b23 = __half22float2(bh[1]);
            float av[4] = {a01.x, a01.y, a23.x, a23.y};
            float bv[4] = {b01.x, b01.y, b23.x, b23.y};
#pragma unroll
            for (int i = 0; i < 4; i++)
#pragma unroll
                for (int j = 0; j < 4; j++) acc[i][j] += av[i] * bv[j];
        }
#pragma unroll
        for (int jj = 0; jj < 4; jj++) {
            int cc = tx * 4 + jj;
            bool msk = (mask[b * SEQ + cc * 8 + jpos] == 0);
#pragma unroll
            for (int i = 0; i < 4; i++)
                Pst[cc * SP68 + ty * 4 + i] = msk ? -1e9f : acc[i][jj] * 0.125f;
        }
        __syncthreads();

        if (tid < 64) {
            float m = -1e30f;
            for (int cc = 0; cc < 64; cc++) m = fmaxf(m, Pst[cc * SP68 + tid]);
            float sum = 0.f;
            for (int cc = 0; cc < 64; cc++) {
                float p = __expf(Pst[cc * SP68 + tid] - m);
                Pst[cc * SP68 + tid] = p; sum += p;
            }
            float inv = 1.f / sum;
            for (int cc = 0; cc < 64; cc++) Pst[cc * SP68 + tid] *= inv;
        }
        __syncthreads();

        for (int idx = tid; idx < 1024; idx += 256) {
            int r = idx >> 4;
            int d0 = (idx & 15) << 2;
            size_t g = (size_t)(b * SEQ + r * 8 + jpos) * DMODEL + h * DKH + d0;
            *(uint2*)&QVh[r * SP68 + d0] = *(const uint2*)(t3 + g);
        }
        __syncthreads();

        PDL_TRIGGER();

        float oacc[4][4];
#pragma unroll
        for (int i = 0; i < 4; i++)
#pragma unroll
            for (int j = 0; j < 4; j++) oacc[i][j] = 0.f;

        for (int kk = 0; kk < 64; kk++) {
            float4 av4 = *(const float4*)&Pst[kk * SP68 + ty * 4];
            uint2 bu = *(const uint2*)&QVh[kk * SP68 + tx * 4];
            const __half2* bh = (const __half2*)&bu;
            float2 b01 = __half22float2(bh[0]), b23 = __half22float2(bh[1]);
            float av[4] = {av4.x, av4.y, av4.z, av4.w};
            float bv[4] = {b01.x, b01.y, b23.x, b23.y};
#pragma unroll
            for (int i = 0; i < 4; i++)
#pragma unroll
                for (int j = 0; j < 4; j++) oacc[i][j] += av[i] * bv[j];
        }
#pragma unroll
        for (int i = 0; i < 4; i++) {
            uint2 ov;
            ((uint32_t*)&ov)[0] = packh2(oacc[i][0], oacc[i][1]);
            ((uint32_t*)&ov)[1] = packh2(oacc[i][2], oacc[i][3]);
            *(uint2*)(ote + (size_t)(b * SEQ + (ty * 4 + i) * 8 + jpos) * DMODEL +
                      h * DKH + tx * 4) = ov;
        }
    }
}

// ---------------------------------------------------------------------------
// LayerNorm: warp-per-row, 8 rows per 256-thread block.
// ---------------------------------------------------------------------------
__global__ __launch_bounds__(256)
void layernorm_kernel(const float* __restrict__ x,
                      const float* __restrict__ gamma,
                      const float* __restrict__ beta,
                      half_t* __restrict__ oh)
{
    int row = blockIdx.x * 8 + (threadIdx.x >> 5);
    int lane = threadIdx.x & 31;
    const float* xr = x + (size_t)row * DMODEL;

    PDL_WAIT();

    float4 v[8];
    float s1 = 0.f, s2 = 0.f;
#pragma unroll
    for (int i = 0; i < 8; i++) {
        v[i] = *(const float4*)(xr + lane * 4 + i * 128);
        s1 += v[i].x + v[i].y + v[i].z + v[i].w;
        s2 += v[i].x * v[i].x + v[i].y * v[i].y + v[i].z * v[i].z + v[i].w * v[i].w;
    }
#pragma unroll
    for (int o = 16; o; o >>= 1) {
        s1 += __shfl_xor_sync(0xffffffffu, s1, o);
        s2 += __shfl_xor_sync(0xffffffffu, s2, o);
    }
    float mean = s1 * (1.f / DMODEL);
    float var = s2 * (1.f / DMODEL) - mean * mean;
    float inv = rsqrtf(var + LN_EPS);

    PDL_TRIGGER();

#pragma unroll
    for (int i = 0; i < 8; i++) {
        int c = lane * 4 + i * 128;
        float4 g = *(const float4*)(gamma + c);
        float4 bb = *(const float4*)(beta + c);
        uint2 ov;
        ((uint32_t*)&ov)[0] = packh2((v[i].x - mean) * inv * g.x + bb.x,
                                     (v[i].y - mean) * inv * g.y + bb.y);
        ((uint32_t*)&ov)[1] = packh2((v[i].z - mean) * inv * g.z + bb.z,
                                     (v[i].w - mean) * inv * g.w + bb.w);
        *(uint2*)(oh + (size_t)row * DMODEL + c) = ov;
    }
}

// ---------------------------------------------------------------------------
// Host orchestration — PDL-attributed launches via cudaLaunchKernelEx
// ---------------------------------------------------------------------------
extern "C" void kernel_launch(void* const* d_in, const int* in_sizes, int n_in,
                              void* d_out, int out_size)
{
    (void)n_in; (void)out_size;
    const float* x    = (const float*)d_in[0];
    const int*   mask = (const int*)  d_in[1];
    const float* sw   = (const float*)d_in[2];
    const float* sb   = (const float*)d_in[3];
    const float* tw   = (const float*)d_in[4];
    const float* tbia = (const float*)d_in[5];
    const float* fw   = (const float*)d_in[6];
    const float* fb   = (const float*)d_in[7];
    const float* aw   = (const float*)d_in[8];
    const float* ab   = (const float*)d_in[9];
    const float* w1   = (const float*)d_in[10];
    const float* b1   = (const float*)d_in[11];
    const float* w2   = (const float*)d_in[12];
    const float* b2   = (const float*)d_in[13];
    const float* lns  = (const float*)d_in[14];
    const float* lnb  = (const float*)d_in[15];
    float* out = (float*)d_out;

    cudaFuncSetAttribute(gemm_hmma<0>, cudaFuncAttributeMaxDynamicSharedMemorySize, SMEM_GEMM);
    cudaFuncSetAttribute(gemm_hmma<1>, cudaFuncAttributeMaxDynamicSharedMemorySize, SMEM_GEMM);
    cudaFuncSetAttribute(gemm_hmma<2>, cudaFuncAttributeMaxDynamicSharedMemorySize, SMEM_GEMM);
    cudaFuncSetAttribute(gemm_hmma<3>, cudaFuncAttributeMaxDynamicSharedMemorySize, SMEM_GEMM);
    cudaFuncSetAttribute(flash_attn,   cudaFuncAttributeMaxDynamicSharedMemorySize, SMEM_FLASH);
    cudaFuncSetAttribute(st_attn,      cudaFuncAttributeMaxDynamicSharedMemorySize, SMEM_STA);

    half_t *wt, *xh, *hh, *ah, *fh, *qkvh, *q, *k, *v, *t1, *t2, *t3;
    float *xb;
    cudaGetSymbolAddress((void**)&wt,   g_wt);
    cudaGetSymbolAddress((void**)&xh,   g_xh);
    cudaGetSymbolAddress((void**)&hh,   g_hh);
    cudaGetSymbolAddress((void**)&ah,   g_ah);
    cudaGetSymbolAddress((void**)&fh,   g_fh);
    cudaGetSymbolAddress((void**)&qkvh, g_qkvh);
    cudaGetSymbolAddress((void**)&q,    g_q);
    cudaGetSymbolAddress((void**)&k,    g_k);
    cudaGetSymbolAddress((void**)&v,    g_v);
    cudaGetSymbolAddress((void**)&t1,   g_t1);
    cudaGetSymbolAddress((void**)&t2,   g_t2);
    cudaGetSymbolAddress((void**)&t3,   g_t3);
    cudaGetSymbolAddress((void**)&xb,   g_xb);

    const size_t DD = (size_t)DMODEL * DMODEL;
    int nlayers = in_sizes[8] / (int)(4 * DD);

    cudaLaunchAttribute pdlAttr;
    pdlAttr.id = cudaLaunchAttributeProgrammaticStreamSerialization;
    pdlAttr.val.programmaticStreamSerializationAllowed = 1;
    auto mkcfg = [&](unsigned gx, unsigned gy, unsigned gz, size_t smem) {
        cudaLaunchConfig_t c = {};
        c.gridDim = dim3(gx, gy, gz);
        c.blockDim = dim3(256, 1, 1);
        c.dynamicSmemBytes = smem;
        c.stream = 0;
        c.attrs = &pdlAttr;
        c.numAttrs = 1;
        return c;
    };

    // Kernels 1-3: plain launches (seal weights before any PDL early-start)
    wconv_all<<<dim3(32, 32, 10 + 12 * nlayers), 256>>>(sw, tw, fw, aw, w1, w2, wt, nlayers);
    aconv_kernel<<<(MTOK * DMODEL / 4 + 255) / 256, 256>>>(x, xh, MTOK * DMODEL);
    gemm_hmma<2><<<dim3(48, 32), 256, SMEM_GEMM>>>(
        xh, wt + OFF_ST, (const half_t*)nullptr, (const half_t*)nullptr, sb, tbia,
        (const float*)nullptr, (float*)nullptr, (half_t*)nullptr,
        MTOK, 6144, DMODEL, 0, 0, q, k, v, t1, t2, t3);

    // PDL-attributed from here on
    {
        cudaLaunchConfig_t c = mkcfg(3072, 1, 1, SMEM_STA);
        cudaLaunchKernelEx(&c, st_attn, (const half_t*)q, (const half_t*)k, (const half_t*)v,
                           (const half_t*)t1, (const half_t*)t2, (const half_t*)t3,
                           mask, (half_t*)ah, (half_t*)hh);
    }
    {
        cudaLaunchConfig_t c = mkcfg(8, 32, 2, SMEM_GEMM);
        cudaLaunchKernelEx(&c, gemm_hmma<3>,
                           (const half_t*)ah, (const half_t*)(wt + OFF_SW3),
                           (const half_t*)hh, (const half_t*)(wt + OFF_TW3),
                           (const float*)(sb + 3 * DMODEL), (const float*)(tbia + 3 * DMODEL),
                           (const float*)nullptr, (float*)nullptr, (half_t*)fh,
                           MTOK, DMODEL, DMODEL, 0, 2048,
                           (half_t*)nullptr, (half_t*)nullptr, (half_t*)nullptr,
                           (half_t*)nullptr, (half_t*)nullptr, (half_t*)nullptr);
    }
    {
        cudaLaunchConfig_t c = mkcfg(8, 32, 1, SMEM_GEMM);
        cudaLaunchKernelEx(&c, gemm_hmma<0>,
                           (const half_t*)fh, (const half_t*)(wt + OFF_FW),
                           (const half_t*)nullptr, (const half_t*)nullptr,
                           fb, (const float*)nullptr,
                           (const float*)nullptr, (float*)xb, (half_t*)nullptr,
                           MTOK, DMODEL, 2 * DMODEL, 0, DMODEL,
                           (half_t*)nullptr, (half_t*)nullptr, (half_t*)nullptr,
                           (half_t*)nullptr, (half_t*)nullptr, (half_t*)nullptr);
    }

    for (int i = 0; i < nlayers; i++) {
        const float* abi = ab + (size_t)i * 4 * DMODEL;
        const half_t* awi = wt + OFF_AW + (size_t)i * 4 * M1;

        {
            cudaLaunchConfig_t c = mkcfg(MTOK / 8, 1, 1, 0);
            cudaLaunchKernelEx(&c, layernorm_kernel, (const float*)xb,
                               (const float*)(lns + (i * 2 + 0) * DMODEL),
                               (const float*)(lnb + (i * 2 + 0) * DMODEL), (half_t*)hh);
        }
        {
            cudaLaunchConfig_t c = mkcfg(24, 32, 1, SMEM_GEMM);
            cudaLaunchKernelEx(&c, gemm_hmma<1>,
                               (const half_t*)hh, (const half_t*)awi,
                               (const half_t*)nullptr, (const half_t*)nullptr,
                               (const float*)abi, (const float*)nullptr,
                               (const float*)nullptr, (float*)nullptr, (half_t*)qkvh,
                               MTOK, 3 * DMODEL, DMODEL, 0, 0,
                               (half_t*)nullptr, (half_t*)nullptr, (half_t*)nullptr,
                               (half_t*)nullptr, (half_t*)nullptr, (half_t*)nullptr);
        }
        {
            cudaLaunchConfig_t c = mkcfg(4, 128, 1, SMEM_FLASH);
            cudaLaunchKernelEx(&c, flash_attn, (const half_t*)qkvh, mask, (half_t*)ah);
        }
        {
            cudaLaunchConfig_t c = mkcfg(8, 32, 1, SMEM_GEMM);
            cudaLaunchKernelEx(&c, gemm_hmma<0>,
                               (const half_t*)ah, (const half_t*)(awi + 3 * M1),
                               (const half_t*)nullptr, (const half_t*)nullptr,
                               (const float*)(abi + 3 * DMODEL), (const float*)nullptr,
                               (const float*)xb, (float*)xb, (half_t*)nullptr,
                               MTOK, DMODEL, DMODEL, 0, DMODEL,
                               (half_t*)nullptr, (half_t*)nullptr, (half_t*)nullptr,
                               (half_t*)nullptr, (half_t*)nullptr, (half_t*)nullptr);
        }
        {
            cudaLaunchConfig_t c = mkcfg(MTOK / 8, 1, 1, 0);
            cudaLaunchKernelEx(&c, layernorm_kernel, (const float*)xb,
                               (const float*)(lns + (i * 2 + 1) * DMODEL),
                               (const float*)(lnb + (i * 2 + 1) * DMODEL), (half_t*)hh);
        }
        {
            cudaLaunchConfig_t c = mkcfg(32, 32, 1, SMEM_GEMM);
            cudaLaunchKernelEx(&c, gemm_hmma<0>,
                               (const half_t*)hh, (const half_t*)(wt + OFF_W1 + (size_t)i * 4 * M1),
                               (const half_t*)nullptr, (const half_t*)nullptr,
                               (const float*)(b1 + i * DFF), (const float*)nullptr,
                               (const float*)nullptr, (float*)nullptr, (half_t*)fh,
                               MTOK, DFF, DMODEL, 1, DFF,
                               (half_t*)nullptr, (half_t*)nullptr, (half_t*)nullptr,
                               (half_t*)nullptr, (half_t*)nullptr, (half_t*)nullptr);
        }
        float* dst = (i == nlayers - 1) ? out : xb;
        {
            cudaLaunchConfig_t c = mkcfg(8, 32, 1, SMEM_GEMM);
            cudaLaunchKernelEx(&c, gemm_hmma<0>,
                               (const half_t*)fh, (const half_t*)(wt + OFF_W2 + (size_t)i * 4 * M1),
                               (const half_t*)nullptr, (const half_t*)nullptr,
                               (const float*)(b2 + i * DMODEL), (const float*)nullptr,
                               (const float*)xb, (float*)dst, (half_t*)nullptr,
                               MTOK, DMODEL, DFF, 0, DMODEL,
                               (half_t*)nullptr, (half_t*)nullptr, (half_t*)nullptr,
                               (half_t*)nullptr, (half_t*)nullptr, (half_t*)nullptr);
        }
    }
}

// round 13
// speedup vs baseline: 1.1035x; 1.0330x over previous
#include <cuda_runtime.h>
#include <cuda_fp16.h>
#include <cstdint>
#include <math.h>

#define DMODEL 1024
#define BATCH  8
#define SEQ    512
#define NHEAD  16
#define DKH    64
#define MTOK   4096
#define DFF    4096
#define NCLIP  64
#define LN_EPS 1e-5f

typedef __half half_t;

// ---------------------------------------------------------------------------
// PTX helpers (arch-agnostic: mma.sync / ldmatrix / cp.async / griddepcontrol)
// ---------------------------------------------------------------------------
__device__ __forceinline__ uint32_t smem_u32(const void* p) {
    uint32_t a;
    asm("{ .reg .u64 t; cvta.to.shared.u64 t, %1; cvt.u32.u64 %0, t; }" : "=r"(a) : "l"(p));
    return a;
}

#define LDSM4(r, a) \
    asm volatile("ldmatrix.sync.aligned.m8n8.x4.shared.b16 {%0,%1,%2,%3}, [%4];" \
        : "=r"((r)[0]), "=r"((r)[1]), "=r"((r)[2]), "=r"((r)[3]) : "r"(a))

#define LDSM4T(r, a) \
    asm volatile("ldmatrix.sync.aligned.m8n8.x4.trans.shared.b16 {%0,%1,%2,%3}, [%4];" \
        : "=r"((r)[0]), "=r"((r)[1]), "=r"((r)[2]), "=r"((r)[3]) : "r"(a))

#define MMA16816(c, a, b0, b1) \
    asm volatile("mma.sync.aligned.m16n8k16.row.col.f32.f16.f16.f32 " \
        "{%0,%1,%2,%3}, {%4,%5,%6,%7}, {%8,%9}, {%0,%1,%2,%3};" \
        : "+f"((c)[0]), "+f"((c)[1]), "+f"((c)[2]), "+f"((c)[3]) \
        : "r"((a)[0]), "r"((a)[1]), "r"((a)[2]), "r"((a)[3]), "r"(b0), "r"(b1))

#define CPASYNC16(d, s) asm volatile("cp.async.cg.shared.global [%0], [%1], 16;" :: "r"(d), "l"(s))
#define CPCOMMIT()      asm volatile("cp.async.commit_group;" ::: "memory")
#define CPWAIT(n)       asm volatile("cp.async.wait_group %0;" :: "n"(n) : "memory")

#define PDL_WAIT()    asm volatile("griddepcontrol.wait;" ::: "memory")
#define PDL_TRIGGER() asm volatile("griddepcontrol.launch_dependents;" ::: "memory")

__device__ __forceinline__ uint32_t packh2(float x, float y) {
    __half2 h = __floats2half2_rn(x, y);
    return *(uint32_t*)&h;
}

// ---------------------------------------------------------------------------
// Device scratch
// ---------------------------------------------------------------------------
#define WT_TOT (34u * 1024u * 1024u)
__device__ half_t g_wt[WT_TOT];
__device__ half_t g_xh[MTOK * DMODEL];
__device__ half_t g_hh[MTOK * DMODEL];
__device__ half_t g_ah[MTOK * DMODEL];
__device__ half_t g_fh[MTOK * DFF];
__device__ half_t g_qkvh[3 * 128 * SEQ * DKH];
__device__ half_t g_q[MTOK * DMODEL];
__device__ half_t g_k[MTOK * DMODEL];
__device__ half_t g_v[MTOK * DMODEL];
__device__ half_t g_t1[MTOK * DMODEL];
__device__ half_t g_t2[MTOK * DMODEL];
__device__ half_t g_t3[MTOK * DMODEL];
__device__ float  g_xb[MTOK * DMODEL];

// weight offsets (units of 1M elements) inside g_wt
#define M1 (1024u * 1024u)
#define DDC (1024u * 1024u)
#define OFF_ST  0u
#define OFF_SW3 (6u * M1)
#define OFF_TW3 (7u * M1)
#define OFF_FW  (8u * M1)
#define OFF_AW  (10u * M1)
#define OFF_W1  (18u * M1)
#define OFF_W2  (26u * M1)

// ---------------------------------------------------------------------------
// fp16 HMMA GEMM, BK=64, 3-stage cp.async, 2 CTAs/SM, PDL:
// B (weights) prefetched before griddepcontrol.wait; A after.
// MODE 0: standard; MODE 1: QKV scatter; MODE 2: six fp16 buffers;
// MODE 3: z-batched out-proj.
// ---------------------------------------------------------------------------
#define STAGES 3
#define STAGE_BYTES 32768
#define SMEM_GEMM (STAGES * STAGE_BYTES)

template<int MODE>
__global__ __launch_bounds__(256, 2)
void gemm_hmma(const half_t* __restrict__ A, const half_t* __restrict__ B,
               const half_t* __restrict__ A2, const half_t* __restrict__ B2,
               const float* __restrict__ bias, const float* __restrict__ bias2,
               const float* __restrict__ R, float* Cf, half_t* Ch,
               int M, int N, int K, int relu, int ldC,
               half_t* q0, half_t* q1, half_t* q2, half_t* q3, half_t* q4, half_t* q5)
{
    extern __shared__ char smem[];
    uint32_t sb = smem_u32(smem);
    const int tid = threadIdx.x;
    const int lane = tid & 31, warp = tid >> 5;
    const int row0 = blockIdx.y * 128, col0 = blockIdx.x * 128;
    const int wm = (warp >> 2) * 64;
    const int wn = (warp & 3) * 32;

    if (MODE == 3 && blockIdx.z == 1) { A = A2; B = B2; bias = bias2; }

    int segr[4], segc[4];
#pragma unroll
    for (int i = 0; i < 4; i++) { int s = tid + i * 256; segr[i] = s >> 3; segc[i] = s & 7; }

    int rA[4], swA[4];
#pragma unroll
    for (int mt = 0; mt < 4; mt++) {
        int r = wm + mt * 16 + (lane & 15);
        rA[mt] = r; swA[mt] = r & 7;
    }
    int rB[2], swB[2];
#pragma unroll
    for (int n2 = 0; n2 < 2; n2++) {
        int r = wn + n2 * 16 + (lane & 7) + ((lane >> 4) << 3);
        rB[n2] = r; swB[n2] = r & 7;
    }
    const int csA = lane >> 4;
    const int csB = (lane >> 3) & 1;

    float acc[4][4][4];
#pragma unroll
    for (int mt = 0; mt < 4; mt++)
#pragma unroll
        for (int nt = 0; nt < 4; nt++)
#pragma unroll
            for (int i = 0; i < 4; i++) acc[mt][nt][i] = 0.f;

    const int NT = K >> 6;

#define GISSUE_B(kt, st) do { \
    uint32_t sB_ = sb + (st) * STAGE_BYTES + 16384; \
    _Pragma("unroll") for (int i = 0; i < 4; i++) { \
        int r_ = segr[i], c_ = segc[i]; \
        uint32_t sw_ = (uint32_t)((c_ ^ (r_ & 7)) << 4); \
        CPASYNC16(sB_ + r_ * 128 + sw_, B + (size_t)(col0 + r_) * K + (size_t)(kt) * 64 + c_ * 8); \
    } \
    CPCOMMIT(); } while (0)

#define GISSUE_A(kt, st) do { \
    uint32_t sA_ = sb + (st) * STAGE_BYTES; \
    _Pragma("unroll") for (int i = 0; i < 4; i++) { \
        int r_ = segr[i], c_ = segc[i]; \
        uint32_t sw_ = (uint32_t)((c_ ^ (r_ & 7)) << 4); \
        CPASYNC16(sA_ + r_ * 128 + sw_, A + (size_t)(row0 + r_) * K + (size_t)(kt) * 64 + c_ * 8); \
    } \
    CPCOMMIT(); } while (0)

#define GISSUE(kt, st) do { \
    uint32_t sA_ = sb + (st) * STAGE_BYTES; \
    uint32_t sB_ = sA_ + 16384; \
    _Pragma("unroll") for (int i = 0; i < 4; i++) { \
        int r_ = segr[i], c_ = segc[i]; \
        uint32_t sw_ = (uint32_t)((c_ ^ (r_ & 7)) << 4); \
        CPASYNC16(sA_ + r_ * 128 + sw_, A + (size_t)(row0 + r_) * K + (size_t)(kt) * 64 + c_ * 8); \
        CPASYNC16(sB_ + r_ * 128 + sw_, B + (size_t)(col0 + r_) * K + (size_t)(kt) * 64 + c_ * 8); \
    } \
    CPCOMMIT(); } while (0)

    GISSUE_B(0, 0);
    GISSUE_B(1, 1);
    PDL_WAIT();
    GISSUE_A(0, 0);
    GISSUE_A(1, 1);

    for (int kt = 0; kt < NT; kt++) {
        if (kt == NT - 1) { CPWAIT(0); } else { CPWAIT(1); }
        __syncthreads();
        if (kt + 2 < NT) GISSUE(kt + 2, (kt + 2) % 3);

        uint32_t sA = sb + (kt % 3) * STAGE_BYTES;
        uint32_t sB = sA + 16384;
#pragma unroll
        for (int k16 = 0; k16 < 4; k16++) {
            uint32_t ra[4][4], rb[2][4];
#pragma unroll
            for (int mt = 0; mt < 4; mt++)
                LDSM4(ra[mt], sA + rA[mt] * 128 + ((((k16 << 1) + csA) ^ swA[mt]) << 4));
#pragma unroll
            for (int n2 = 0; n2 < 2; n2++)
                LDSM4(rb[n2], sB + rB[n2] * 128 + ((((k16 << 1) + csB) ^ swB[n2]) << 4));
#pragma unroll
            for (int mt = 0; mt < 4; mt++)
#pragma unroll
                for (int nt = 0; nt < 4; nt++)
                    MMA16816(acc[mt][nt], ra[mt],
                             rb[nt >> 1][(nt & 1) * 2], rb[nt >> 1][(nt & 1) * 2 + 1]);
        }
    }

    PDL_TRIGGER();

    // Epilogue
    half_t* obuf = nullptr;
    if (MODE == 2) {
        int bsel = col0 >> 10;
        obuf = (bsel == 0) ? q0 : (bsel == 1) ? q1 : (bsel == 2) ? q2 :
               (bsel == 3) ? q3 : (bsel == 4) ? q4 : q5;
    }
    const int cbase = (MODE == 3) ? (int)blockIdx.z * 1024 : 0;
#pragma unroll
    for (int mt = 0; mt < 4; mt++) {
        int rg = row0 + wm + mt * 16 + (lane >> 2);
#pragma unroll
        for (int nt = 0; nt < 4; nt++) {
            int c = col0 + wn + nt * 8 + (lane & 3) * 2;
            float* a = acc[mt][nt];
#pragma unroll
            for (int h = 0; h < 2; h++) {
                int row = rg + h * 8;
                float v0 = a[h * 2], v1 = a[h * 2 + 1];
                if (MODE == 0) {
                    if (bias) { v0 += bias[c]; v1 += bias[c + 1]; }
                    if (R) {
                        float2 rr = *(const float2*)(R + (size_t)row * N + c);
                        v0 += rr.x; v1 += rr.y;
                    }
                    if (relu) { v0 = fmaxf(v0, 0.f); v1 = fmaxf(v1, 0.f); }
                    if (Cf) {
                        float2 o; o.x = v0; o.y = v1;
                        *(float2*)(Cf + (size_t)row * ldC + c) = o;
                    }
                    if (Ch)
                        *(__half2*)(Ch + (size_t)row * ldC + c) = __floats2half2_rn(v0, v1);
                } else if (MODE == 1) {
                    v0 += bias[c]; v1 += bias[c + 1];
                    int qkv = c >> 10, hh_ = (c >> 6) & 15, d = c & 63;
                    int b = row >> 9, srow = row & 511;
                    size_t dst = (((size_t)(qkv * 128 + b * 16 + hh_) * 512) + srow) * 64 + d;
                    *(__half2*)(Ch + dst) = __floats2half2_rn(v0, v1);
                } else if (MODE == 2) {
                    float b0v = (c < 3072) ? bias[c] : bias2[c - 3072];
                    float b1v = (c + 1 < 3072) ? bias[c + 1] : bias2[c + 1 - 3072];
                    *(__half2*)(obuf + (size_t)row * 1024 + (c & 1023)) =
                        __floats2half2_rn(v0 + b0v, v1 + b1v);
                } else { // MODE 3
                    v0 += bias[c]; v1 += bias[c + 1];
                    *(__half2*)(Ch + (size_t)row * ldC + cbase + c) = __floats2half2_rn(v0, v1);
                }
            }
        }
    }
}

// ---------------------------------------------------------------------------
// Flash attention (encoder): per (b,h) 512x512, fp16 mma, online softmax.
// ---------------------------------------------------------------------------
#define FLD 72
#define SMEM_FLASH (3 * 128 * FLD * 2 + 512)

__global__ __launch_bounds__(256)
void flash_attn(const half_t* __restrict__ qkvh, const int* __restrict__ mask,
                half_t* __restrict__ out)
{
    extern __shared__ char sm[];
    half_t* Qs = (half_t*)sm;
    half_t* Ks = Qs + 128 * FLD;
    half_t* Vs = Ks + 128 * FLD;
    float*  mf = (float*)(Vs + 128 * FLD);

    const int bh = blockIdx.y, qt = blockIdx.x;
    const int b = bh >> 4, hd = bh & 15;
    const int tid = threadIdx.x, lane = tid & 31, warp = tid >> 5;
    const int m0 = warp * 16;

    PDL_WAIT();

    const half_t* Qg = qkvh + (((size_t)(0 * 128 + bh) * 512) + qt * 128) * 64;
    const half_t* Kg = qkvh + ((size_t)(1 * 128 + bh) * 512) * 64;
    const half_t* Vg = qkvh + ((size_t)(2 * 128 + bh) * 512) * 64;

    for (int i = tid; i < 1024; i += 256) {
        int r = i >> 3, cs = i & 7;
        *(uint4*)(Qs + r * FLD + cs * 8) = *(const uint4*)(Qg + r * 64 + cs * 8);
    }
    __syncthreads();

    uint32_t qf[4][4];
#pragma unroll
    for (int kb = 0; kb < 4; kb++)
        LDSM4(qf[kb], smem_u32(Qs + (m0 + (lane & 15)) * FLD + kb * 16 + (lane >> 4) * 8));

    float mrow[2] = {-1e30f, -1e30f};
    float lrow[2] = {0.f, 0.f};
    float oacc[8][4];
#pragma unroll
    for (int i = 0; i < 8; i++)
#pragma unroll
        for (int j = 0; j < 4; j++) oacc[i][j] = 0.f;

    for (int kt = 0; kt < 4; kt++) {
        __syncthreads();
        for (int i = tid; i < 1024; i += 256) {
            int r = i >> 3, cs = i & 7;
            *(uint4*)(Ks + r * FLD + cs * 8) = *(const uint4*)(Kg + (kt * 128 + r) * 64 + cs * 8);
            *(uint4*)(Vs + r * FLD + cs * 8) = *(const uint4*)(Vg + (kt * 128 + r) * 64 + cs * 8);
        }
        if (tid < 128) mf[tid] = (mask[b * SEQ + kt * 128 + tid] == 0) ? 1.f : 0.f;
        __syncthreads();

        float s[16][4];
#pragma unroll
        for (int f = 0; f < 16; f++)
#pragma unroll
            for (int i = 0; i < 4; i++) s[f][i] = 0.f;

#pragma unroll
        for (int kb = 0; kb < 4; kb++) {
#pragma unroll
            for (int nb2 = 0; nb2 < 8; nb2++) {
                uint32_t bf[4];
                int krow = nb2 * 16 + (lane & 7) + ((lane >> 4) & 1) * 8;
                int kcol = kb * 16 + ((lane >> 3) & 1) * 8;
                LDSM4(bf, smem_u32(Ks + krow * FLD + kcol));
                MMA16816(s[2 * nb2],     qf[kb], bf[0], bf[1]);
                MMA16816(s[2 * nb2 + 1], qf[kb], bf[2], bf[3]);
            }
        }

#pragma unroll
        for (int f = 0; f < 16; f++) {
            int c0 = f * 8 + (lane & 3) * 2;
            float f0 = mf[c0], f1 = mf[c0 + 1];
            s[f][0] = (f0 != 0.f) ? -1e9f : s[f][0] * 0.125f;
            s[f][1] = (f1 != 0.f) ? -1e9f : s[f][1] * 0.125f;
            s[f][2] = (f0 != 0.f) ? -1e9f : s[f][2] * 0.125f;
            s[f][3] = (f1 != 0.f) ? -1e9f : s[f][3] * 0.125f;
        }

        float mx0 = -1e30f, mx1 = -1e30f;
#pragma unroll
        for (int f = 0; f < 16; f++) {
            mx0 = fmaxf(mx0, fmaxf(s[f][0], s[f][1]));
            mx1 = fmaxf(mx1, fmaxf(s[f][2], s[f][3]));
        }
        mx0 = fmaxf(mx0, __shfl_xor_sync(0xffffffffu, mx0, 1));
        mx0 = fmaxf(mx0, __shfl_xor_sync(0xffffffffu, mx0, 2));
        mx1 = fmaxf(mx1, __shfl_xor_sync(0xffffffffu, mx1, 1));
        mx1 = fmaxf(mx1, __shfl_xor_sync(0xffffffffu, mx1, 2));

        float Mn0 = fmaxf(mrow[0], mx0), Mn1 = fmaxf(mrow[1], mx1);
        float sc0 = __expf(mrow[0] - Mn0), sc1 = __expf(mrow[1] - Mn1);
        mrow[0] = Mn0; mrow[1] = Mn1;

        float rs0 = 0.f, rs1 = 0.f;
#pragma unroll
        for (int f = 0; f < 16; f++) {
            s[f][0] = __expf(s[f][0] - Mn0); s[f][1] = __expf(s[f][1] - Mn0);
            s[f][2] = __expf(s[f][2] - Mn1); s[f][3] = __expf(s[f][3] - Mn1);
            rs0 += s[f][0] + s[f][1];
            rs1 += s[f][2] + s[f][3];
        }
        rs0 += __shfl_xor_sync(0xffffffffu, rs0, 1);
        rs0 += __shfl_xor_sync(0xffffffffu, rs0, 2);
        rs1 += __shfl_xor_sync(0xffffffffu, rs1, 1);
        rs1 += __shfl_xor_sync(0xffffffffu, rs1, 2);
        lrow[0] = lrow[0] * sc0 + rs0;
        lrow[1] = lrow[1] * sc1 + rs1;

#pragma unroll
        for (int nb = 0; nb < 8; nb++) {
            oacc[nb][0] *= sc0; oacc[nb][1] *= sc0;
            oacc[nb][2] *= sc1; oacc[nb][3] *= sc1;
        }

#pragma unroll
        for (int kb = 0; kb < 8; kb++) {
            uint32_t a[4];
            a[0] = packh2(s[2 * kb][0],     s[2 * kb][1]);
            a[1] = packh2(s[2 * kb][2],     s[2 * kb][3]);
            a[2] = packh2(s[2 * kb + 1][0], s[2 * kb + 1][1]);
            a[3] = packh2(s[2 * kb + 1][2], s[2 * kb + 1][3]);
#pragma unroll
            for (int nb2 = 0; nb2 < 4; nb2++) {
                uint32_t vf[4];
                int srow = kb * 16 + (lane & 15);
                int dcol = nb2 * 16 + (lane >> 4) * 8;
                LDSM4T(vf, smem_u32(Vs + srow * FLD + dcol));
                MMA16816(oacc[2 * nb2],     a, vf[0], vf[1]);
                MMA16816(oacc[2 * nb2 + 1], a, vf[2], vf[3]);
            }
        }
    }

    PDL_TRIGGER();

    float inv0 = 1.f / lrow[0], inv1 = 1.f / lrow[1];
    int r0 = qt * 128 + m0 + (lane >> 2);
#pragma unroll
    for (int nb = 0; nb < 8; nb++) {
        int c = hd * 64 + nb * 8 + (lane & 3) * 2;
        *(__half2*)(out + (size_t)(b * SEQ + r0) * DMODEL + c) =
            __floats2half2_rn(oacc[nb][0] * inv0, oacc[nb][1] * inv0);
        *(__half2*)(out + (size_t)(b * SEQ + r0 + 8) * DMODEL + c) =
            __floats2half2_rn(oacc[nb][2] * inv1, oacc[nb][3] * inv1);
    }
}

// ---------------------------------------------------------------------------
// ALL conversions in one launch: weight transposes (vectorized, stride-33
// smem) + x cast units appended at the end.
// ---------------------------------------------------------------------------
__global__ void wconv_all(const float* __restrict__ sw, const float* __restrict__ tw,
                          const float* __restrict__ fw, const float* __restrict__ aw,
                          const float* __restrict__ w1, const float* __restrict__ w2,
                          const float* __restrict__ x,
                          half_t* __restrict__ wt, half_t* __restrict__ xh,
                          int nlayers)
{
    __shared__ float t[32 * 33];
    int uid = blockIdx.z;
    int A = 10 + 4 * nlayers;
    int Bu = A + 4 * nlayers;
    int Xc = Bu + 4 * nlayers;       // start of x-cast units (4 units)
    int tid = threadIdx.x;

    if (uid >= Xc) {
        // cast-only: 1M elements per unit, tile = by*32+bx -> 1024 elems
        size_t base = (size_t)(uid - Xc) * M1 +
                      ((size_t)(blockIdx.y * 32 + blockIdx.x)) * 1024 + tid * 4;
        float4 v = *(const float4*)(x + base);
        *(__half2*)(xh + base)     = __floats2half2_rn(v.x, v.y);
        *(__half2*)(xh + base + 2) = __floats2half2_rn(v.z, v.w);
        return;
    }

    const float* src;
    size_t dsto;
    int Ns, Kd;
    if (uid < 6) {
        src = (uid < 3) ? (sw + (size_t)uid * DDC) : (tw + (size_t)(uid - 3) * DDC);
        dsto = OFF_ST + (size_t)uid * M1; Ns = 1024; Kd = 1024;
    } else if (uid == 6) {
        src = sw + 3 * (size_t)DDC; dsto = OFF_SW3; Ns = 1024; Kd = 1024;
    } else if (uid == 7) {
        src = tw + 3 * (size_t)DDC; dsto = OFF_TW3; Ns = 1024; Kd = 1024;
    } else if (uid < 10) {
        int c = uid - 8;
        src = fw + (size_t)c * 1024 * 1024; dsto = OFF_FW + (size_t)c * 1024;
        Ns = 1024; Kd = 2048;
    } else if (uid < A) {
        int j = uid - 10;
        src = aw + (size_t)j * DDC; dsto = OFF_AW + (size_t)j * M1; Ns = 1024; Kd = 1024;
    } else if (uid < Bu) {
        int tix = uid - A; int i = tix >> 2, c = tix & 3;
        src = w1 + (size_t)i * 4 * M1 + (size_t)c * 1024;
        dsto = OFF_W1 + (size_t)i * 4 * M1 + (size_t)c * M1;
        Ns = 4096; Kd = 1024;
    } else {
        int tix = uid - Bu; int i = tix >> 2, c = tix & 3;
        src = w2 + (size_t)i * 4 * M1 + (size_t)c * M1;
        dsto = OFF_W2 + (size_t)i * 4 * M1 + (size_t)c * 1024;
        Ns = 1024; Kd = 4096;
    }

    int n0 = blockIdx.x * 32, k0 = blockIdx.y * 32;

    // Load: one float4 per thread (row r = k, 4 consecutive n), scatter to
    // stride-33 smem (scalar stores).
    {
        int r = tid >> 3, c4 = (tid & 7) * 4;
        float4 v = *(const float4*)(src + (size_t)(k0 + r) * Ns + n0 + c4);
        t[r * 33 + c4 + 0] = v.x;
        t[r * 33 + c4 + 1] = v.y;
        t[r * 33 + c4 + 2] = v.z;
        t[r * 33 + c4 + 3] = v.w;
    }
    __syncthreads();

    // Store: each thread packs 4 k-consecutive halves for one n (uint2 STG).
    {
        int n = tid >> 3, kg = tid & 7;
        float f0 = t[(kg * 4 + 0) * 33 + n];
        float f1 = t[(kg * 4 + 1) * 33 + n];
        float f2 = t[(kg * 4 + 2) * 33 + n];
        float f3 = t[(kg * 4 + 3) * 33 + n];
        uint2 ov;
        ((uint32_t*)&ov)[0] = packh2(f0, f1);
        ((uint32_t*)&ov)[1] = packh2(f2, f3);
        *(uint2*)(wt + dsto + (size_t)(n0 + n) * Kd + k0 + kg * 4) = ov;
    }
}

// ---------------------------------------------------------------------------
// Merged spatial+temporal attention.
// ---------------------------------------------------------------------------
#define SP68 68
#define SMEM_STA 34816

__global__ __launch_bounds__(256)
void st_attn(const half_t* __restrict__ q, const half_t* __restrict__ k,
             const half_t* __restrict__ v,
             const half_t* __restrict__ t1, const half_t* __restrict__ t2,
             const half_t* __restrict__ t3,
             const int* __restrict__ mask,
             half_t* __restrict__ osp, half_t* __restrict__ ote)
{
    extern __shared__ float S[];
    int tid = threadIdx.x;

    PDL_WAIT();

    if (blockIdx.x < 2048) {
        int unit = tid >> 6, tu = tid & 63;
        int u = blockIdx.x * 4 + unit;
        int h = u & 15;
        int c = (u >> 4) & 63;
        int b = u >> 10;
        int tb = b * SEQ + c * 8;
        float* Qs = S + unit * 1696;
        float* Ks = Qs + 544;
        float* Vs = Ks + 544;
        float* Ps = Vs + 544;

        {
            int r = tu >> 3, d0 = (tu & 7) * 8;
            size_t g = (size_t)(tb + r) * DMODEL + h * DKH + d0;
            uint4 qv = *(const uint4*)(q + g);
            uint4 kv = *(const uint4*)(k + g);
            uint4 vv = *(const uint4*)(v + g);
            const __half2* qh = (const __half2*)&qv;
            const __half2* kh = (const __half2*)&kv;
            const __half2* vh = (const __half2*)&vv;
#pragma unroll
            for (int j = 0; j < 4; j++) {
                float2 f = __half22float2(qh[j]);
                Qs[r * SP68 + d0 + 2 * j] = f.x; Qs[r * SP68 + d0 + 2 * j + 1] = f.y;
                f = __half22float2(kh[j]);
                Ks[r * SP68 + d0 + 2 * j] = f.x; Ks[r * SP68 + d0 + 2 * j + 1] = f.y;
                f = __half22float2(vh[j]);
                Vs[r * SP68 + d0 + 2 * j] = f.x; Vs[r * SP68 + d0 + 2 * j + 1] = f.y;
            }
        }
        __syncthreads();

        int i = tu >> 3, j = tu & 7;
        float4 a4; a4.x = 0.f; a4.y = 0.f; a4.z = 0.f; a4.w = 0.f;
#pragma unroll
        for (int d = 0; d < 64; d += 4) {
            float4 qa = *(const float4*)&Qs[i * SP68 + d];
            float4 kb = *(const float4*)&Ks[j * SP68 + d];
            a4.x += qa.x * kb.x; a4.y += qa.y * kb.y;
            a4.z += qa.z * kb.z; a4.w += qa.w * kb.w;
        }
        float s = (a4.x + a4.y + a4.z + a4.w) * 0.125f;
        if (mask[b * SEQ + c * 8 + j] == 0) s = -1e9f;

        float m = s;
        m = fmaxf(m, __shfl_xor_sync(0xffffffffu, m, 1));
        m = fmaxf(m, __shfl_xor_sync(0xffffffffu, m, 2));
        m = fmaxf(m, __shfl_xor_sync(0xffffffffu, m, 4));
        float p = __expf(s - m);
        float sum = p;
        sum += __shfl_xor_sync(0xffffffffu, sum, 1);
        sum += __shfl_xor_sync(0xffffffffu, sum, 2);
        sum += __shfl_xor_sync(0xffffffffu, sum, 4);
        Ps[i * 8 + j] = p / sum;
        __syncthreads();

        PDL_TRIGGER();

        {
            int r = tu >> 3, d0 = (tu & 7) * 8;
            float4 o0, o1;
            o0.x = o0.y = o0.z = o0.w = 0.f;
            o1.x = o1.y = o1.z = o1.w = 0.f;
#pragma unroll
            for (int jj = 0; jj < 8; jj++) {
                float pv = Ps[r * 8 + jj];
                float4 v0 = *(const float4*)&Vs[jj * SP68 + d0];
                float4 v1 = *(const float4*)&Vs[jj * SP68 + d0 + 4];
                o0.x += pv * v0.x; o0.y += pv * v0.y; o0.z += pv * v0.z; o0.w += pv * v0.w;
                o1.x += pv * v1.x; o1.y += pv * v1.y; o1.z += pv * v1.z; o1.w += pv * v1.w;
            }
            uint4 ov;
            ((uint32_t*)&ov)[0] = packh2(o0.x, o0.y);
            ((uint32_t*)&ov)[1] = packh2(o0.z, o0.w);
            ((uint32_t*)&ov)[2] = packh2(o1.x, o1.y);
            ((uint32_t*)&ov)[3] = packh2(o1.z, o1.w);
            *(uint4*)(osp + (size_t)(tb + r) * DMODEL + h * DKH + d0) = ov;
        }
    } else {
        int u = blockIdx.x - 2048;
        int h = u & 15;
        int jpos = (u >> 4) & 7;
        int b = u >> 7;
        int tx = tid & 15, ty = tid >> 4;
        half_t* QVh  = (half_t*)S;
        half_t* Ks2h = QVh + 64 * SP68;
        float*  Pst  = (float*)(Ks2h + 64 * SP68);

        for (int idx = tid; idx < 1024; idx += 256) {
            int r = idx >> 4;
            int d0 = (idx & 15) << 2;
            size_t g = (size_t)(b * SEQ + r * 8 + jpos) * DMODEL + h * DKH + d0;
            uint2 av = *(const uint2*)(t1 + g);
            const half_t* ah = (const half_t*)&av;
            QVh[(d0 + 0) * SP68 + r] = ah[0];
            QVh[(d0 + 1) * SP68 + r] = ah[1];
            QVh[(d0 + 2) * SP68 + r] = ah[2];
            QVh[(d0 + 3) * SP68 + r] = ah[3];
            uint2 kv = *(const uint2*)(t2 + g);
            const half_t* kh = (const half_t*)&kv;
            Ks2h[(d0 + 0) * SP68 + r] = kh[0];
            Ks2h[(d0 + 1) * SP68 + r] = kh[1];
            Ks2h[(d0 + 2) * SP68 + r] = kh[2];
            Ks2h[(d0 + 3) * SP68 + r] = kh[3];
        }
        __syncthreads();

        float acc[4][4];
#pragma unroll
        for (int i = 0; i < 4; i++)
#pragma unroll
            for (int j = 0; j < 4; j++) acc[i][j] = 0.f;

        for (int d = 0; d < 64; d++) {
            uint2 au = *(const uint2*)&QVh[d * SP68 + ty * 4];
            uint2 bu = *(const uint2*)&Ks2h[d * SP68 + tx * 4];
            const __half2* ah = (const __half2*)&au;
            const __half2* bh = (const __half2*)&bu;
            float2 a01 = __half22float2(ah[0]), a23 = __half22float2(ah[1]);
            float2 b01 = __half22float2(bh[0]), b23 = __half22float2(bh[1]);
            float av[4] = {a01.x, a01.y, a23.x, a23.y};
            float bv[4] = {b01.x, b01.y, b23.x, b23.y};
#pragma unroll
            for (int i = 0; i < 4; i++)
#pragma unroll
                for (int j = 0; j < 4; j++) acc[i][j] += av[i] * bv[j];
        }
#pragma unroll
        for (int jj = 0; jj < 4; jj++) {
            int cc = tx * 4 + jj;
            bool msk = (mask[b * SEQ + cc * 8 + jpos] == 0);
#pragma unroll
            for (int i = 0; i < 4; i++)
                Pst[cc * SP68 + ty * 4 + i] = msk ? -1e9f : acc[i][jj] * 0.125f;
        }
        __syncthreads();

        if (tid < 64) {
            float m = -1e30f;
            for (int cc = 0; cc < 64; cc++) m = fmaxf(m, Pst[cc * SP68 + tid]);
            float sum = 0.f;
            for (int cc = 0; cc < 64; cc++) {
                float p = __expf(Pst[cc * SP68 + tid] - m);
                Pst[cc * SP68 + tid] = p; sum += p;
            }
            float inv = 1.f / sum;
            for (int cc = 0; cc < 64; cc++) Pst[cc * SP68 + tid] *= inv;
        }
        __syncthreads();

        for (int idx = tid; idx < 1024; idx += 256) {
            int r = idx >> 4;
            int d0 = (idx & 15) << 2;
            size_t g = (size_t)(b * SEQ + r * 8 + jpos) * DMODEL + h * DKH + d0;
            *(uint2*)&QVh[r * SP68 + d0] = *(const uint2*)(t3 + g);
        }
        __syncthreads();

        PDL_TRIGGER();

        float oacc[4][4];
#pragma unroll
        for (int i = 0; i < 4; i++)
#pragma unroll
            for (int j = 0; j < 4; j++) oacc[i][j] = 0.f;

        for (int kk = 0; kk < 64; kk++) {
            float4 av4 = *(const float4*)&Pst[kk * SP68 + ty * 4];
            uint2 bu = *(const uint2*)&QVh[kk * SP68 + tx * 4];
            const __half2* bh = (const __half2*)&bu;
            float2 b01 = __half22float2(bh[0]), b23 = __half22float2(bh[1]);
            float av[4] = {av4.x, av4.y, av4.z, av4.w};
            float bv[4] = {b01.x, b01.y, b23.x, b23.y};
#pragma unroll
            for (int i = 0; i < 4; i++)
#pragma unroll
                for (int j = 0; j < 4; j++) oacc[i][j] += av[i] * bv[j];
        }
#pragma unroll
        for (int i = 0; i < 4; i++) {
            uint2 ov;
            ((uint32_t*)&ov)[0] = packh2(oacc[i][0], oacc[i][1]);
            ((uint32_t*)&ov)[1] = packh2(oacc[i][2], oacc[i][3]);
            *(uint2*)(ote + (size_t)(b * SEQ + (ty * 4 + i) * 8 + jpos) * DMODEL +
                      h * DKH + tx * 4) = ov;
        }
    }
}

// ---------------------------------------------------------------------------
// LayerNorm: warp-per-row, 8 rows per 256-thread block.
// ---------------------------------------------------------------------------
__global__ __launch_bounds__(256)
void layernorm_kernel(const float* __restrict__ x,
                      const float* __restrict__ gamma,
                      const float* __restrict__ beta,
                      half_t* __restrict__ oh)
{
    int row = blockIdx.x * 8 + (threadIdx.x >> 5);
    int lane = threadIdx.x & 31;
    const float* xr = x + (size_t)row * DMODEL;

    PDL_WAIT();

    float4 v[8];
    float s1 = 0.f, s2 = 0.f;
#pragma unroll
    for (int i = 0; i < 8; i++) {
        v[i] = *(const float4*)(xr + lane * 4 + i * 128);
        s1 += v[i].x + v[i].y + v[i].z + v[i].w;
        s2 += v[i].x * v[i].x + v[i].y * v[i].y + v[i].z * v[i].z + v[i].w * v[i].w;
    }
#pragma unroll
    for (int o = 16; o; o >>= 1) {
        s1 += __shfl_xor_sync(0xffffffffu, s1, o);
        s2 += __shfl_xor_sync(0xffffffffu, s2, o);
    }
    float mean = s1 * (1.f / DMODEL);
    float var = s2 * (1.f / DMODEL) - mean * mean;
    float inv = rsqrtf(var + LN_EPS);

    PDL_TRIGGER();

#pragma unroll
    for (int i = 0; i < 8; i++) {
        int c = lane * 4 + i * 128;
        float4 g = *(const float4*)(gamma + c);
        float4 bb = *(const float4*)(beta + c);
        uint2 ov;
        ((uint32_t*)&ov)[0] = packh2((v[i].x - mean) * inv * g.x + bb.x,
                                     (v[i].y - mean) * inv * g.y + bb.y);
        ((uint32_t*)&ov)[1] = packh2((v[i].z - mean) * inv * g.z + bb.z,
                                     (v[i].w - mean) * inv * g.w + bb.w);
        *(uint2*)(oh + (size_t)row * DMODEL + c) = ov;
    }
}

// ---------------------------------------------------------------------------
// Host orchestration — PDL-attributed launches via cudaLaunchKernelEx
// ---------------------------------------------------------------------------
extern "C" void kernel_launch(void* const* d_in, const int* in_sizes, int n_in,
                              void* d_out, int out_size)
{
    (void)n_in; (void)out_size;
    const float* x    = (const float*)d_in[0];
    const int*   mask = (const int*)  d_in[1];
    const float* sw   = (const float*)d_in[2];
    const float* sb   = (const float*)d_in[3];
    const float* tw   = (const float*)d_in[4];
    const float* tbia = (const float*)d_in[5];
    const float* fw   = (const float*)d_in[6];
    const float* fb   = (const float*)d_in[7];
    const float* aw   = (const float*)d_in[8];
    const float* ab   = (const float*)d_in[9];
    const float* w1   = (const float*)d_in[10];
    const float* b1   = (const float*)d_in[11];
    const float* w2   = (const float*)d_in[12];
    const float* b2   = (const float*)d_in[13];
    const float* lns  = (const float*)d_in[14];
    const float* lnb  = (const float*)d_in[15];
    float* out = (float*)d_out;

    cudaFuncSetAttribute(gemm_hmma<0>, cudaFuncAttributeMaxDynamicSharedMemorySize, SMEM_GEMM);
    cudaFuncSetAttribute(gemm_hmma<1>, cudaFuncAttributeMaxDynamicSharedMemorySize, SMEM_GEMM);
    cudaFuncSetAttribute(gemm_hmma<2>, cudaFuncAttributeMaxDynamicSharedMemorySize, SMEM_GEMM);
    cudaFuncSetAttribute(gemm_hmma<3>, cudaFuncAttributeMaxDynamicSharedMemorySize, SMEM_GEMM);
    cudaFuncSetAttribute(flash_attn,   cudaFuncAttributeMaxDynamicSharedMemorySize, SMEM_FLASH);
    cudaFuncSetAttribute(st_attn,      cudaFuncAttributeMaxDynamicSharedMemorySize, SMEM_STA);

    half_t *wt, *xh, *hh, *ah, *fh, *qkvh, *q, *k, *v, *t1, *t2, *t3;
    float *xb;
    cudaGetSymbolAddress((void**)&wt,   g_wt);
    cudaGetSymbolAddress((void**)&xh,   g_xh);
    cudaGetSymbolAddress((void**)&hh,   g_hh);
    cudaGetSymbolAddress((void**)&ah,   g_ah);
    cudaGetSymbolAddress((void**)&fh,   g_fh);
    cudaGetSymbolAddress((void**)&qkvh, g_qkvh);
    cudaGetSymbolAddress((void**)&q,    g_q);
    cudaGetSymbolAddress((void**)&k,    g_k);
    cudaGetSymbolAddress((void**)&v,    g_v);
    cudaGetSymbolAddress((void**)&t1,   g_t1);
    cudaGetSymbolAddress((void**)&t2,   g_t2);
    cudaGetSymbolAddress((void**)&t3,   g_t3);
    cudaGetSymbolAddress((void**)&xb,   g_xb);

    const size_t DD = (size_t)DMODEL * DMODEL;
    int nlayers = in_sizes[8] / (int)(4 * DD);

    cudaLaunchAttribute pdlAttr;
    pdlAttr.id = cudaLaunchAttributeProgrammaticStreamSerialization;
    pdlAttr.val.programmaticStreamSerializationAllowed = 1;
    auto mkcfg = [&](unsigned gx, unsigned gy, unsigned gz, size_t smem) {
        cudaLaunchConfig_t c = {};
        c.gridDim = dim3(gx, gy, gz);
        c.blockDim = dim3(256, 1, 1);
        c.dynamicSmemBytes = smem;
        c.stream = 0;
        c.attrs = &pdlAttr;
        c.numAttrs = 1;
        return c;
    };

    // Kernels 1-2: plain (seal weights + xh before any PDL early-start)
    wconv_all<<<dim3(32, 32, 14 + 12 * nlayers), 256>>>(sw, tw, fw, aw, w1, w2, x,
                                                        wt, xh, nlayers);
    gemm_hmma<2><<<dim3(48, 32), 256, SMEM_GEMM>>>(
        xh, wt + OFF_ST, (const half_t*)nullptr, (const half_t*)nullptr, sb, tbia,
        (const float*)nullptr, (float*)nullptr, (half_t*)nullptr,
        MTOK, 6144, DMODEL, 0, 0, q, k, v, t1, t2, t3);

    // PDL-attributed from here on
    {
        cudaLaunchConfig_t c = mkcfg(3072, 1, 1, SMEM_STA);
        cudaLaunchKernelEx(&c, st_attn, (const half_t*)q, (const half_t*)k, (const half_t*)v,
                           (const half_t*)t1, (const half_t*)t2, (const half_t*)t3,
                           mask, (half_t*)ah, (half_t*)hh);
    }
    {
        cudaLaunchConfig_t c = mkcfg(8, 32, 2, SMEM_GEMM);
        cudaLaunchKernelEx(&c, gemm_hmma<3>,
                           (const half_t*)ah, (const half_t*)(wt + OFF_SW3),
                           (const half_t*)hh, (const half_t*)(wt + OFF_TW3),
                           (const float*)(sb + 3 * DMODEL), (const float*)(tbia + 3 * DMODEL),
                           (const float*)nullptr, (float*)nullptr, (half_t*)fh,
                           MTOK, DMODEL, DMODEL, 0, 2048,
                           (half_t*)nullptr, (half_t*)nullptr, (half_t*)nullptr,
                           (half_t*)nullptr, (half_t*)nullptr, (half_t*)nullptr);
    }
    {
        cudaLaunchConfig_t c = mkcfg(8, 32, 1, SMEM_GEMM);
        cudaLaunchKernelEx(&c, gemm_hmma<0>,
                           (const half_t*)fh, (const half_t*)(wt + OFF_FW),
                           (const half_t*)nullptr, (const half_t*)nullptr,
                           fb, (const float*)nullptr,
                           (const float*)nullptr, (float*)xb, (half_t*)nullptr,
                           MTOK, DMODEL, 2 * DMODEL, 0, DMODEL,
                           (half_t*)nullptr, (half_t*)nullptr, (half_t*)nullptr,
                           (half_t*)nullptr, (half_t*)nullptr, (half_t*)nullptr);
    }

    for (int i = 0; i < nlayers; i++) {
        const float* abi = ab + (size_t)i * 4 * DMODEL;
        const half_t* awi = wt + OFF_AW + (size_t)i * 4 * M1;

        {
            cudaLaunchConfig_t c = mkcfg(MTOK / 8, 1, 1, 0);
            cudaLaunchKernelEx(&c, layernorm_kernel, (const float*)xb,
                               (const float*)(lns + (i * 2 + 0) * DMODEL),
                               (const float*)(lnb + (i * 2 + 0) * DMODEL), (half_t*)hh);
        }
        {
            cudaLaunchConfig_t c = mkcfg(24, 32, 1, SMEM_GEMM);
            cudaLaunchKernelEx(&c, gemm_hmma<1>,
                               (const half_t*)hh, (const half_t*)awi,
                               (const half_t*)nullptr, (const half_t*)nullptr,
                               (const float*)abi, (const float*)nullptr,
                               (const float*)nullptr, (float*)nullptr, (half_t*)qkvh,
                               MTOK, 3 * DMODEL, DMODEL, 0, 0,
                               (half_t*)nullptr, (half_t*)nullptr, (half_t*)nullptr,
                               (half_t*)nullptr, (half_t*)nullptr, (half_t*)nullptr);
        }
        {
            cudaLaunchConfig_t c = mkcfg(4, 128, 1, SMEM_FLASH);
            cudaLaunchKernelEx(&c, flash_attn, (const half_t*)qkvh, mask, (half_t*)ah);
        }
        {
            cudaLaunchConfig_t c = mkcfg(8, 32, 1, SMEM_GEMM);
            cudaLaunchKernelEx(&c, gemm_hmma<0>,
                               (const half_t*)ah, (const half_t*)(awi + 3 * M1),
                               (const half_t*)nullptr, (const half_t*)nullptr,
                               (const float*)(abi + 3 * DMODEL), (const float*)nullptr,
                               (const float*)xb, (float*)xb, (half_t*)nullptr,
                               MTOK, DMODEL, DMODEL, 0, DMODEL,
                               (half_t*)nullptr, (half_t*)nullptr, (half_t*)nullptr,
                               (half_t*)nullptr, (half_t*)nullptr, (half_t*)nullptr);
        }
        {
            cudaLaunchConfig_t c = mkcfg(MTOK / 8, 1, 1, 0);
            cudaLaunchKernelEx(&c, layernorm_kernel, (const float*)xb,
                               (const float*)(lns + (i * 2 + 1) * DMODEL),
                               (const float*)(lnb + (i * 2 + 1) * DMODEL), (half_t*)hh);
        }
        {
            cudaLaunchConfig_t c = mkcfg(32, 32, 1, SMEM_GEMM);
            cudaLaunchKernelEx(&c, gemm_hmma<0>,
                               (const half_t*)hh, (const half_t*)(wt + OFF_W1 + (size_t)i * 4 * M1),
                               (const half_t*)nullptr, (const half_t*)nullptr,
                               (const float*)(b1 + i * DFF), (const float*)nullptr,
                               (const float*)nullptr, (float*)nullptr, (half_t*)fh,
                               MTOK, DFF, DMODEL, 1, DFF,
                               (half_t*)nullptr, (half_t*)nullptr, (half_t*)nullptr,
                               (half_t*)nullptr, (half_t*)nullptr, (half_t*)nullptr);
        }
        float* dst = (i == nlayers - 1) ? out : xb;
        {
            cudaLaunchConfig_t c = mkcfg(8, 32, 1, SMEM_GEMM);
            cudaLaunchKernelEx(&c, gemm_hmma<0>,
                               (const half_t*)fh, (const half_t*)(wt + OFF_W2 + (size_t)i * 4 * M1),
                               (const half_t*)nullptr, (const half_t*)nullptr,
                               (const float*)(b2 + i * DMODEL), (const float*)nullptr,
                               (const float*)xb, (float*)dst, (half_t*)nullptr,
                               MTOK, DMODEL, DFF, 0, DMODEL,
                               (half_t*)nullptr, (half_t*)nullptr, (half_t*)nullptr,
                               (half_t*)nullptr, (half_t*)nullptr, (half_t*)nullptr);
        }
    }
}